// round 11
// baseline (speedup 1.0000x reference)
#include <cuda_runtime.h>
#include <cuda_bf16.h>
#include <cuda_fp16.h>
#include <cstdint>

// ===================== device scratch (static, no allocation) =====================
__device__ __align__(16) float g_xw[2048 * 2048];
__device__ __align__(16) float g_cat[2048 * 1024];
__device__ __align__(16) float g_scores[16 * 128 * 128];
__device__ __align__(16) float g_encT[16 * 512 * 128];
__device__ __align__(16) float g_whhT[512 * 2048];
__device__ __align__(16) float g_hbuf[512 * 16];
__device__ __align__(16) float g_bcomb[2048];
__device__ unsigned g_bar;

// bf16 3-term operands (small GEMMs)
__device__ __align__(16) __nv_bfloat16 s_emb_h[2048 * 256],  s_emb_l[2048 * 256];
__device__ __align__(16) __nv_bfloat16 s_wih_h[2048 * 256],  s_wih_l[2048 * 256];
__device__ __align__(16) __nv_bfloat16 s_cat_h[2048 * 1024], s_cat_l[2048 * 1024];
__device__ __align__(16) __nv_bfloat16 s_enc_h[16 * 128 * 512], s_enc_l[16 * 128 * 512];
__device__ __align__(16) __nv_bfloat16 s_encT_h[16 * 512 * 128], s_encT_l[16 * 512 * 128];
__device__ __align__(16) __nv_bfloat16 s_sc_h[16 * 128 * 128], s_sc_l[16 * 128 * 128];

// fp16 operands (output projection)
__device__ __align__(16) __half s_cat16[2048 * 1024];
__device__ __align__(16) __half s_wout16[32000 * 1024];

// ===================== helpers =====================
__device__ __forceinline__ float sigm(float x) { return 1.f / (1.f + expf(-x)); }

__device__ __forceinline__ void mma16b(float* d, const uint32_t* a, const uint32_t* b) {
    asm volatile(
        "mma.sync.aligned.m16n8k16.row.col.f32.bf16.bf16.f32 "
        "{%0,%1,%2,%3}, {%4,%5,%6,%7}, {%8,%9}, {%0,%1,%2,%3};"
        : "+f"(d[0]), "+f"(d[1]), "+f"(d[2]), "+f"(d[3])
        : "r"(a[0]), "r"(a[1]), "r"(a[2]), "r"(a[3]), "r"(b[0]), "r"(b[1]));
}

__device__ __forceinline__ void mma16h(float* d, const uint32_t* a, const uint32_t* b) {
    asm volatile(
        "mma.sync.aligned.m16n8k16.row.col.f32.f16.f16.f32 "
        "{%0,%1,%2,%3}, {%4,%5,%6,%7}, {%8,%9}, {%0,%1,%2,%3};"
        : "+f"(d[0]), "+f"(d[1]), "+f"(d[2]), "+f"(d[3])
        : "r"(a[0]), "r"(a[1]), "r"(a[2]), "r"(a[3]), "r"(b[0]), "r"(b[1]));
}

__device__ __forceinline__ void ldsm4(uint32_t& r0, uint32_t& r1, uint32_t& r2, uint32_t& r3,
                                      uint32_t addr) {
    asm volatile("ldmatrix.sync.aligned.m8n8.x4.shared.b16 {%0,%1,%2,%3}, [%4];"
                 : "=r"(r0), "=r"(r1), "=r"(r2), "=r"(r3) : "r"(addr));
}

__device__ __forceinline__ void cpasync16(uint32_t dst, const void* src) {
    asm volatile("cp.async.cg.shared.global [%0], [%1], 16;" :: "r"(dst), "l"(src));
}

// ===================== gemmh: fp16 1-term out-GEMM (128x128 tile, 3-stage, 2 CTA/SM) ====
#define HPITCH 80
#define H_AB (128 * HPITCH)
#define HSTG (2 * H_AB)
#define HSMEM (3 * HSTG)

__global__ void __launch_bounds__(256, 2) gemmh(
    const __half* __restrict__ Ag, const __half* __restrict__ Bg,
    float* __restrict__ C, const float* __restrict__ bias,
    int K, int lda, int ldb, int ldc)
{
    extern __shared__ char smc[];
    const uint32_t sb = (uint32_t)__cvta_generic_to_shared(smc);

    const int m0 = blockIdx.x * 128, n0 = blockIdx.y * 128;
    const int tid = threadIdx.x, lane = tid & 31, warp = tid >> 5;
    const int wm = (warp & 1) * 64, wn = (warp >> 1) * 32;
    const int gid = lane >> 2, tig = lane & 3;
    const int rsel = lane & 15, csel = (lane >> 4) * 16;
    const int KT = K >> 5;

    float acc[4][4][4];
#pragma unroll
    for (int a = 0; a < 4; a++)
#pragma unroll
        for (int b = 0; b < 4; b++)
#pragma unroll
            for (int d = 0; d < 4; d++) acc[a][b][d] = 0.f;

#define HLOAD(KT_IDX, ST)                                                              \
    {                                                                                  \
        const int kof = (KT_IDX) * 32;                                                 \
        const uint32_t st = sb + (ST) * HSTG;                                          \
        _Pragma("unroll")                                                              \
        for (int i = 0; i < 2; i++) {                                                  \
            const int c = tid + 256 * i;                                               \
            const int row = c >> 2, off = c & 3;                                       \
            const uint32_t ad = st + row * HPITCH + off * 16;                          \
            cpasync16(ad,        Ag + (long long)(m0 + row) * lda + kof + off * 8);    \
            cpasync16(ad + H_AB, Bg + (long long)(n0 + row) * ldb + kof + off * 8);    \
        }                                                                              \
        asm volatile("cp.async.commit_group;");                                        \
    }

    HLOAD(0, 0);
    HLOAD(1, 1);

    for (int kt = 0; kt < KT; kt++) {
        if (kt + 2 < KT) asm volatile("cp.async.wait_group 1;");
        else             asm volatile("cp.async.wait_group 0;");
        __syncthreads();
        if (kt + 2 < KT) HLOAD(kt + 2, (kt + 2) % 3);

        const uint32_t base = sb + (kt % 3) * HSTG;
#pragma unroll
        for (int k16 = 0; k16 < 2; k16++) {
            const uint32_t kof = k16 * 32 + csel;
            uint32_t bh[4][2];
#pragma unroll
            for (int np = 0; np < 2; np++) {
                const uint32_t rb = base + H_AB + (wn + np * 16 + rsel) * HPITCH + kof;
                uint32_t t0, t1, t2, t3;
                ldsm4(t0, t1, t2, t3, rb);
                bh[2 * np][0] = t0; bh[2 * np][1] = t2;
                bh[2 * np + 1][0] = t1; bh[2 * np + 1][1] = t3;
            }
            uint32_t ah[4][4];
#pragma unroll
            for (int mf = 0; mf < 4; mf++) {
                const uint32_t ra = base + (wm + mf * 16 + rsel) * HPITCH + kof;
                ldsm4(ah[mf][0], ah[mf][1], ah[mf][2], ah[mf][3], ra);
            }
#pragma unroll
            for (int mf = 0; mf < 4; mf++)
#pragma unroll
                for (int nf = 0; nf < 4; nf++)
                    mma16h(acc[mf][nf], ah[mf], bh[nf]);
        }
    }

#pragma unroll
    for (int mf = 0; mf < 4; mf++) {
        const int r = m0 + wm + mf * 16 + gid;
#pragma unroll
        for (int nf = 0; nf < 4; nf++) {
            const int c = n0 + wn + nf * 8 + 2 * tig;
            float b0 = bias[c], b1 = bias[c + 1];
            float2 v0 = {acc[mf][nf][0] + b0, acc[mf][nf][1] + b1};
            float2 v1 = {acc[mf][nf][2] + b0, acc[mf][nf][3] + b1};
            *(float2*)&C[(long long)r * ldc + c] = v0;
            *(float2*)&C[(long long)(r + 8) * ldc + c] = v1;
        }
    }
}

// ===================== gemmb: bf16 3-term (small/batched GEMMs) =====
#define PITCH 80
#define MAT_B (128 * PITCH)
#define STG_B (4 * MAT_B)

__global__ void __launch_bounds__(256, 2) gemmb(
    const __nv_bfloat16* __restrict__ Ahg, const __nv_bfloat16* __restrict__ Alg,
    const __nv_bfloat16* __restrict__ Bhg, const __nv_bfloat16* __restrict__ Blg,
    float* __restrict__ C, const float* __restrict__ bias,
    int K, int lda, int ldb, int ldc,
    long long sA, long long sB, long long sC, float alpha)
{
    extern __shared__ char smc[];
    const uint32_t sb = (uint32_t)__cvta_generic_to_shared(smc);

    Ahg += sA * blockIdx.z; Alg += sA * blockIdx.z;
    Bhg += sB * blockIdx.z; Blg += sB * blockIdx.z;
    C += sC * blockIdx.z;

    const int m0 = blockIdx.x * 128, n0 = blockIdx.y * 128;
    const int tid = threadIdx.x, lane = tid & 31, warp = tid >> 5;
    const int wm = (warp & 1) * 64, wn = (warp >> 1) * 32;
    const int gid = lane >> 2, tig = lane & 3;
    const int rsel = lane & 15, csel = (lane >> 4) * 16;
    const int KT = K >> 5;
    const int lrow = tid >> 2, loff = tid & 3;

    float acc[4][4][4];
#pragma unroll
    for (int a = 0; a < 4; a++)
#pragma unroll
        for (int b = 0; b < 4; b++)
#pragma unroll
            for (int d = 0; d < 4; d++) acc[a][b][d] = 0.f;

#define LOAD_STAGE(KT_IDX, ST)                                                          \
    {                                                                                   \
        const int kofs = (KT_IDX) * 32 + loff * 8;                                      \
        const uint32_t db = sb + (ST) * STG_B + lrow * PITCH + loff * 16;               \
        cpasync16(db,                  Ahg + (long long)(m0 + lrow) * lda + kofs);      \
        cpasync16(db + 64 * PITCH,     Ahg + (long long)(m0 + lrow + 64) * lda + kofs); \
        cpasync16(db + MAT_B,          Alg + (long long)(m0 + lrow) * lda + kofs);      \
        cpasync16(db + MAT_B + 64 * PITCH, Alg + (long long)(m0 + lrow + 64) * lda + kofs); \
        cpasync16(db + 2 * MAT_B,      Bhg + (long long)(n0 + lrow) * ldb + kofs);      \
        cpasync16(db + 2 * MAT_B + 64 * PITCH, Bhg + (long long)(n0 + lrow + 64) * ldb + kofs); \
        cpasync16(db + 3 * MAT_B,      Blg + (long long)(n0 + lrow) * ldb + kofs);      \
        cpasync16(db + 3 * MAT_B + 64 * PITCH, Blg + (long long)(n0 + lrow + 64) * ldb + kofs); \
        asm volatile("cp.async.commit_group;");                                         \
    }

    LOAD_STAGE(0, 0);

    for (int kt = 0; kt < KT; kt++) {
        if (kt + 1 < KT) {
            LOAD_STAGE(kt + 1, (kt + 1) & 1);
            asm volatile("cp.async.wait_group 1;");
        } else {
            asm volatile("cp.async.wait_group 0;");
        }
        __syncthreads();

        const uint32_t base = sb + (kt & 1) * STG_B;
#pragma unroll
        for (int k16 = 0; k16 < 2; k16++) {
            const uint32_t kof = k16 * 32 + csel;
            uint32_t bh[4][2], bl[4][2];
#pragma unroll
            for (int np = 0; np < 2; np++) {
                const uint32_t rb = base + 2 * MAT_B + (wn + np * 16 + rsel) * PITCH + kof;
                uint32_t t0, t1, t2, t3;
                ldsm4(t0, t1, t2, t3, rb);
                bh[2 * np][0] = t0; bh[2 * np][1] = t2;
                bh[2 * np + 1][0] = t1; bh[2 * np + 1][1] = t3;
                ldsm4(t0, t1, t2, t3, rb + MAT_B);
                bl[2 * np][0] = t0; bl[2 * np][1] = t2;
                bl[2 * np + 1][0] = t1; bl[2 * np + 1][1] = t3;
            }
#pragma unroll
            for (int mg = 0; mg < 2; mg++) {
                uint32_t ah[2][4], al[2][4];
#pragma unroll
                for (int mi = 0; mi < 2; mi++) {
                    const uint32_t ra = base + (wm + (mg * 2 + mi) * 16 + rsel) * PITCH + kof;
                    ldsm4(ah[mi][0], ah[mi][1], ah[mi][2], ah[mi][3], ra);
                    ldsm4(al[mi][0], al[mi][1], al[mi][2], al[mi][3], ra + MAT_B);
                }
#pragma unroll
                for (int mi = 0; mi < 2; mi++)
#pragma unroll
                    for (int nf = 0; nf < 4; nf++)
                        mma16b(acc[mg * 2 + mi][nf], ah[mi], bh[nf]);
#pragma unroll
                for (int mi = 0; mi < 2; mi++)
#pragma unroll
                    for (int nf = 0; nf < 4; nf++)
                        mma16b(acc[mg * 2 + mi][nf], ah[mi], bl[nf]);
#pragma unroll
                for (int mi = 0; mi < 2; mi++)
#pragma unroll
                    for (int nf = 0; nf < 4; nf++)
                        mma16b(acc[mg * 2 + mi][nf], al[mi], bh[nf]);
            }
        }
        __syncthreads();
    }

#pragma unroll
    for (int mf = 0; mf < 4; mf++) {
        const int r = m0 + wm + mf * 16 + gid;
#pragma unroll
        for (int nf = 0; nf < 4; nf++) {
            const int c = n0 + wn + nf * 8 + 2 * tig;
            float b0 = bias ? bias[c] : 0.f;
            float b1 = bias ? bias[c + 1] : 0.f;
            float2 v0 = {alpha * acc[mf][nf][0] + b0, alpha * acc[mf][nf][1] + b1};
            float2 v1 = {alpha * acc[mf][nf][2] + b0, alpha * acc[mf][nf][3] + b1};
            *(float2*)&C[(long long)r * ldc + c] = v0;
            *(float2*)&C[(long long)(r + 8) * ldc + c] = v1;
        }
    }
}

// ===================== split / convert kernels =====================
__global__ void k_split(const float4* __restrict__ in, __nv_bfloat162* __restrict__ hi,
                        __nv_bfloat162* __restrict__ lo, int n4) {
    int i = blockIdx.x * 256 + threadIdx.x;
    if (i >= n4) return;
    float4 v = in[i];
    __nv_bfloat16 h0 = __float2bfloat16(v.x), h1 = __float2bfloat16(v.y);
    __nv_bfloat16 h2 = __float2bfloat16(v.z), h3 = __float2bfloat16(v.w);
    hi[2 * i]     = __nv_bfloat162(h0, h1);
    hi[2 * i + 1] = __nv_bfloat162(h2, h3);
    lo[2 * i]     = __nv_bfloat162(__float2bfloat16(v.x - __bfloat162float(h0)),
                                   __float2bfloat16(v.y - __bfloat162float(h1)));
    lo[2 * i + 1] = __nv_bfloat162(__float2bfloat16(v.z - __bfloat162float(h2)),
                                   __float2bfloat16(v.w - __bfloat162float(h3)));
}

__global__ void k_half(const float4* __restrict__ in, __half2* __restrict__ out, int n4) {
    int i = blockIdx.x * 256 + threadIdx.x;
    if (i >= n4) return;
    float4 v = in[i];
    out[2 * i]     = __half2(__float2half_rn(v.x), __float2half_rn(v.y));
    out[2 * i + 1] = __half2(__float2half_rn(v.z), __float2half_rn(v.w));
}

// ===================== consolidated init: emb gather+split, Wih split, bcomb/hbuf ====
__global__ void k_init(const int* __restrict__ y, const float* __restrict__ tab,
                       const float4* __restrict__ Wih,
                       const float* __restrict__ bih, const float* __restrict__ bhh) {
    const int bk = blockIdx.x, tid = threadIdx.x;
    if (bk < 512) {  // emb gather + bf16 split
        int i = bk * 256 + tid;
        int bs = i >> 6, e = i & 63;
        float4 v = ((const float4*)(tab + (long long)y[bs] * 256))[e];
        __nv_bfloat16 h0 = __float2bfloat16(v.x), h1 = __float2bfloat16(v.y);
        __nv_bfloat16 h2 = __float2bfloat16(v.z), h3 = __float2bfloat16(v.w);
        ((__nv_bfloat162*)s_emb_h)[2 * i]     = __nv_bfloat162(h0, h1);
        ((__nv_bfloat162*)s_emb_h)[2 * i + 1] = __nv_bfloat162(h2, h3);
        ((__nv_bfloat162*)s_emb_l)[2 * i]     = __nv_bfloat162(__float2bfloat16(v.x - __bfloat162float(h0)),
                                                               __float2bfloat16(v.y - __bfloat162float(h1)));
        ((__nv_bfloat162*)s_emb_l)[2 * i + 1] = __nv_bfloat162(__float2bfloat16(v.z - __bfloat162float(h2)),
                                                               __float2bfloat16(v.w - __bfloat162float(h3)));
    } else if (bk < 1024) {  // Wih bf16 split
        int i = (bk - 512) * 256 + tid;
        float4 v = Wih[i];
        __nv_bfloat16 h0 = __float2bfloat16(v.x), h1 = __float2bfloat16(v.y);
        __nv_bfloat16 h2 = __float2bfloat16(v.z), h3 = __float2bfloat16(v.w);
        ((__nv_bfloat162*)s_wih_h)[2 * i]     = __nv_bfloat162(h0, h1);
        ((__nv_bfloat162*)s_wih_h)[2 * i + 1] = __nv_bfloat162(h2, h3);
        ((__nv_bfloat162*)s_wih_l)[2 * i]     = __nv_bfloat162(__float2bfloat16(v.x - __bfloat162float(h0)),
                                                               __float2bfloat16(v.y - __bfloat162float(h1)));
        ((__nv_bfloat162*)s_wih_l)[2 * i + 1] = __nv_bfloat162(__float2bfloat16(v.z - __bfloat162float(h2)),
                                                               __float2bfloat16(v.w - __bfloat162float(h3)));
    } else {  // biases, h state, barrier
        int i = (bk - 1024) * 256 + tid;
        if (i < 2048) g_bcomb[i] = bih[i] + bhh[i];
        if (i < 8192) g_hbuf[i] = 0.f;
        if (i == 0) g_bar = 0;
    }
}

__global__ void k_transpose(const float* __restrict__ in, float* __restrict__ out, int R, int C) {
    __shared__ float t[32][33];
    in += (long long)blockIdx.z * R * C;
    out += (long long)blockIdx.z * R * C;
    int c0 = blockIdx.x * 32, r0 = blockIdx.y * 32;
    int x = threadIdx.x, y = threadIdx.y;
#pragma unroll
    for (int i = 0; i < 32; i += 8)
        if (r0 + y + i < R && c0 + x < C) t[y + i][x] = in[(r0 + y + i) * C + c0 + x];
    __syncthreads();
#pragma unroll
    for (int i = 0; i < 32; i += 8)
        if (c0 + y + i < C && r0 + x < R) out[(c0 + y + i) * R + r0 + x] = t[x][y + i];
}

// softmax: reads g_scores fp32, writes probs DIRECTLY as bf16 hi/lo (no fp32 writeback)
__global__ void k_softmax(const uint32_t* __restrict__ mask) {
    int w = (blockIdx.x * blockDim.x + threadIdx.x) >> 5;
    int lane = threadIdx.x & 31;
    if (w >= 2048) return;
    int b = w >> 7;
    const float* row = g_scores + w * 128;
    const uint32_t* m = mask + b * 128;
    float v[4];
    float mx = -1e30f;
#pragma unroll
    for (int i = 0; i < 4; i++) {
        int l = lane + 32 * i;
        v[i] = (m[l] != 0u) ? row[l] : -1e9f;
        mx = fmaxf(mx, v[i]);
    }
#pragma unroll
    for (int o = 16; o > 0; o >>= 1) mx = fmaxf(mx, __shfl_xor_sync(0xffffffffu, mx, o));
    float s = 0.f;
#pragma unroll
    for (int i = 0; i < 4; i++) { v[i] = expf(v[i] - mx); s += v[i]; }
#pragma unroll
    for (int o = 16; o > 0; o >>= 1) s += __shfl_xor_sync(0xffffffffu, s, o);
    float inv = 1.f / s;
#pragma unroll
    for (int i = 0; i < 4; i++) {
        float p = v[i] * inv;
        __nv_bfloat16 h = __float2bfloat16(p);
        int idx = w * 128 + lane + 32 * i;
        s_sc_h[idx] = h;
        s_sc_l[idx] = __float2bfloat16(p - __bfloat162float(h));
    }
}

// ===================== persistent LSTM + fused W_out fp16 convert =====================
__device__ __forceinline__ void gridbar(unsigned target) {
    __syncthreads();
    if (threadIdx.x == 0) {
        __threadfence();
        atomicAdd(&g_bar, 1);
        while (*(volatile unsigned*)&g_bar < target) __nanosleep(32);
        __threadfence();
    }
    __syncthreads();
}

#define SPLIT_BLOCKS 256

__global__ void __launch_bounds__(256) lstm_kernel(
    const float* __restrict__ xw,
    const float4* __restrict__ wout, __half2* __restrict__ wo16)
{
    const int tid = threadIdx.x, bk = blockIdx.x;

    if (bk >= 128) {  // W_out -> fp16 converter
        for (int i = (bk - 128) * 256 + tid; i < 8192000; i += SPLIT_BLOCKS * 256) {
            float4 v = wout[i];
            wo16[2 * i]     = __half2(__float2half_rn(v.x), __float2half_rn(v.y));
            wo16[2 * i + 1] = __half2(__float2half_rn(v.z), __float2half_rn(v.w));
        }
        return;
    }

    extern __shared__ float smf[];
    float* h_sm = smf;
    float* red = smf + 8192;
    float* sgate = smf + 8192 + 4096;

    const int ks = tid >> 4;
    const int bg = (tid >> 2) & 3;
    const int jg = tid & 3;
    const int u0 = bk * 4;
    const int b0 = bg * 4;
    const int rj = tid >> 4, rb = tid & 15;
    const int puu = tid >> 4, pbb = tid & 15;
    float creg = 0.f;

    for (int t = 0; t < 128; t++) {
        // h broadcast load, float4 (8 per thread)
#pragma unroll
        for (int i = tid; i < 2048; i += 256)
            ((float4*)h_sm)[i] = ((const float4*)g_hbuf)[i];
        __syncthreads();

        float a[4][4];
#pragma unroll
        for (int jj = 0; jj < 4; jj++)
#pragma unroll
            for (int bb = 0; bb < 4; bb++) a[jj][bb] = 0.f;

        const float* wp = g_whhT + (ks * 32) * 2048 + jg * 512 + u0;
        const float* hp = h_sm + (ks * 32) * 16 + b0;
#pragma unroll 8
        for (int k = 0; k < 32; k++) {
            float4 wv = *(const float4*)wp;
            float4 hv = *(const float4*)hp;
            wp += 2048; hp += 16;
            float wa[4] = {wv.x, wv.y, wv.z, wv.w};
            float ha[4] = {hv.x, hv.y, hv.z, hv.w};
#pragma unroll
            for (int jj = 0; jj < 4; jj++)
#pragma unroll
                for (int bb = 0; bb < 4; bb++) a[jj][bb] = fmaf(wa[jj], ha[bb], a[jj][bb]);
        }
#pragma unroll
        for (int jj = 0; jj < 4; jj++)
#pragma unroll
            for (int bb = 0; bb < 4; bb++)
                red[ks * 256 + (jg * 4 + jj) * 16 + (bg * 4 + bb)] = a[jj][bb];
        __syncthreads();

        float s = 0.f;
#pragma unroll
        for (int q = 0; q < 16; q++) s += red[q * 256 + rj * 16 + rb];
        const int g = rj >> 2, uu = rj & 3;
        s += xw[(rb * 128 + t) * 2048 + g * 512 + u0 + uu];
        sgate[rj * 16 + rb] = s;
        __syncthreads();

        if (tid < 64) {
            float gi = sgate[(0 * 4 + puu) * 16 + pbb];
            float gf = sgate[(1 * 4 + puu) * 16 + pbb];
            float gg = sgate[(2 * 4 + puu) * 16 + pbb];
            float go = sgate[(3 * 4 + puu) * 16 + pbb];
            creg = sigm(gf) * creg + sigm(gi) * tanhf(gg);
            float h = sigm(go) * tanhf(creg);
            g_hbuf[(u0 + puu) * 16 + pbb] = h;
            g_cat[(pbb * 128 + t) * 1024 + u0 + puu] = h;
        }
        gridbar(128u * (t + 1));
    }
}

// ===================== host launcher =====================
extern "C" void kernel_launch(void* const* d_in, const int* in_sizes, int n_in,
                              void* d_out, int out_size) {
    const int* y = (const int*)d_in[0];
    const float* tab = (const float*)d_in[1];
    const float* Wih = (const float*)d_in[2];
    const float* Whh = (const float*)d_in[3];
    const float* bih = (const float*)d_in[4];
    const float* bhh = (const float*)d_in[5];
    const float* enc = (const float*)d_in[6];
    const uint32_t* mask = (const uint32_t*)d_in[7];
    const float* Wout = (const float*)d_in[8];
    const float* bout = (const float*)d_in[9];
    float* out = (float*)d_out;

    float *p_xw, *p_cat, *p_scores, *p_encT, *p_whhT, *p_bcomb;
    cudaGetSymbolAddress((void**)&p_xw, g_xw);
    cudaGetSymbolAddress((void**)&p_cat, g_cat);
    cudaGetSymbolAddress((void**)&p_scores, g_scores);
    cudaGetSymbolAddress((void**)&p_encT, g_encT);
    cudaGetSymbolAddress((void**)&p_whhT, g_whhT);
    cudaGetSymbolAddress((void**)&p_bcomb, g_bcomb);

    __nv_bfloat16 *e_h, *e_l, *wi_h, *wi_l, *c_h, *c_l;
    __nv_bfloat16 *en_h, *en_l, *et_h, *et_l, *sc_h, *sc_l;
    cudaGetSymbolAddress((void**)&e_h, s_emb_h);   cudaGetSymbolAddress((void**)&e_l, s_emb_l);
    cudaGetSymbolAddress((void**)&wi_h, s_wih_h);  cudaGetSymbolAddress((void**)&wi_l, s_wih_l);
    cudaGetSymbolAddress((void**)&c_h, s_cat_h);   cudaGetSymbolAddress((void**)&c_l, s_cat_l);
    cudaGetSymbolAddress((void**)&en_h, s_enc_h);  cudaGetSymbolAddress((void**)&en_l, s_enc_l);
    cudaGetSymbolAddress((void**)&et_h, s_encT_h); cudaGetSymbolAddress((void**)&et_l, s_encT_l);
    cudaGetSymbolAddress((void**)&sc_h, s_sc_h);   cudaGetSymbolAddress((void**)&sc_l, s_sc_l);

    __half *c16, *wo16;
    cudaGetSymbolAddress((void**)&c16, s_cat16);
    cudaGetSymbolAddress((void**)&wo16, s_wout16);

    cudaFuncSetAttribute(gemmb, cudaFuncAttributeMaxDynamicSharedMemorySize, 2 * STG_B);
    cudaFuncSetAttribute(gemmh, cudaFuncAttributeMaxDynamicSharedMemorySize, HSMEM);
    cudaFuncSetAttribute(lstm_kernel, cudaFuncAttributeMaxDynamicSharedMemorySize, 53248);

    // #1: consolidated init (emb gather+split, Wih split, bcomb/hbuf/bar)
    k_init<<<1056, 256>>>(y, tab, (const float4*)Wih, bih, bhh);

    // #2: xw = emb @ W_ih^T + (b_ih + b_hh)   [bf16 3-term]
    gemmb<<<dim3(16, 16, 1), 256, 2 * STG_B>>>(e_h, e_l, wi_h, wi_l, p_xw, p_bcomb,
                                               256, 256, 256, 2048, 0, 0, 0, 1.f);

    // #3: W_hh transpose
    k_transpose<<<dim3(16, 64, 1), dim3(32, 8)>>>(Whh, p_whhT, 2048, 512);

    // #4: LSTM + fused W_out fp16 conversion   <-- ncu-profiled launch
    lstm_kernel<<<128 + SPLIT_BLOCKS, 256, 53248>>>(p_xw, (const float4*)Wout, (__half2*)wo16);

    // enc prep (independent of LSTM output)
    k_transpose<<<dim3(16, 4, 16), dim3(32, 8)>>>(enc, p_encT, 128, 512);
    k_split<<<1024, 256>>>((const float4*)enc, (__nv_bfloat162*)en_h, (__nv_bfloat162*)en_l, 262144);
    k_split<<<1024, 256>>>((const float4*)p_encT, (__nv_bfloat162*)et_h, (__nv_bfloat162*)et_l, 262144);

    k_split<<<2048, 256>>>((const float4*)p_cat, (__nv_bfloat162*)c_h, (__nv_bfloat162*)c_l, 524288);

    // scores = dec @ enc^T / sqrt(H)        [bf16 3-term]
    gemmb<<<dim3(1, 1, 16), 256, 2 * STG_B>>>(c_h, c_l, en_h, en_l, p_scores, nullptr,
                                              512, 1024, 512, 128,
                                              131072LL, 65536LL, 16384LL,
                                              0.044194173824159216f);
    // softmax (emits probs directly as bf16 hi/lo)
    k_softmax<<<256, 256>>>(mask);

    // context = probs @ enc                 [bf16 3-term]
    gemmb<<<dim3(1, 4, 16), 256, 2 * STG_B>>>(sc_h, sc_l, et_h, et_l, p_cat + 512, nullptr,
                                              128, 128, 128, 1024,
                                              16384LL, 65536LL, 131072LL, 1.f);

    // cat -> fp16 for output projection
    k_half<<<2048, 256>>>((const float4*)p_cat, (__half2*)c16, 524288);

    // logits = cat @ W_out^T + b_out        [fp16 1-term]
    gemmh<<<dim3(16, 250), 256, HSMEM>>>(c16, wo16, out, bout, 1024, 1024, 1024, 32000);
}

// round 12
// speedup vs baseline: 1.3475x; 1.3475x over previous
#include <cuda_runtime.h>
#include <cuda_bf16.h>
#include <cuda_fp16.h>
#include <cstdint>

// ===================== device scratch (static, no allocation) =====================
__device__ __align__(16) float g_xw[2048 * 2048];
__device__ __align__(16) float g_cat[2048 * 1024];
__device__ __align__(16) float g_scores[16 * 128 * 128];
__device__ __align__(16) float g_encT[16 * 512 * 128];
__device__ __align__(16) float g_whhT[512 * 2048];
__device__ __align__(16) float g_hbuf[512 * 16];
__device__ __align__(16) float g_bcomb[2048];
__device__ unsigned g_bar;

// bf16 3-term operands (small GEMMs)
__device__ __align__(16) __nv_bfloat16 s_emb_h[2048 * 256],  s_emb_l[2048 * 256];
__device__ __align__(16) __nv_bfloat16 s_wih_h[2048 * 256],  s_wih_l[2048 * 256];
__device__ __align__(16) __nv_bfloat16 s_cat_h[2048 * 1024], s_cat_l[2048 * 1024];
__device__ __align__(16) __nv_bfloat16 s_enc_h[16 * 128 * 512], s_enc_l[16 * 128 * 512];
__device__ __align__(16) __nv_bfloat16 s_encT_h[16 * 512 * 128], s_encT_l[16 * 512 * 128];
__device__ __align__(16) __nv_bfloat16 s_sc_h[16 * 128 * 128], s_sc_l[16 * 128 * 128];

// fp16 operands (output projection)
__device__ __align__(16) __half s_cat16[2048 * 1024];
__device__ __align__(16) __half s_wout16[32000 * 1024];

// ===================== helpers =====================
__device__ __forceinline__ float sigm(float x) { return 1.f / (1.f + expf(-x)); }

__device__ __forceinline__ void mma16b(float* d, const uint32_t* a, const uint32_t* b) {
    asm volatile(
        "mma.sync.aligned.m16n8k16.row.col.f32.bf16.bf16.f32 "
        "{%0,%1,%2,%3}, {%4,%5,%6,%7}, {%8,%9}, {%0,%1,%2,%3};"
        : "+f"(d[0]), "+f"(d[1]), "+f"(d[2]), "+f"(d[3])
        : "r"(a[0]), "r"(a[1]), "r"(a[2]), "r"(a[3]), "r"(b[0]), "r"(b[1]));
}

__device__ __forceinline__ void mma16h(float* d, const uint32_t* a, const uint32_t* b) {
    asm volatile(
        "mma.sync.aligned.m16n8k16.row.col.f32.f16.f16.f32 "
        "{%0,%1,%2,%3}, {%4,%5,%6,%7}, {%8,%9}, {%0,%1,%2,%3};"
        : "+f"(d[0]), "+f"(d[1]), "+f"(d[2]), "+f"(d[3])
        : "r"(a[0]), "r"(a[1]), "r"(a[2]), "r"(a[3]), "r"(b[0]), "r"(b[1]));
}

__device__ __forceinline__ void ldsm4(uint32_t& r0, uint32_t& r1, uint32_t& r2, uint32_t& r3,
                                      uint32_t addr) {
    asm volatile("ldmatrix.sync.aligned.m8n8.x4.shared.b16 {%0,%1,%2,%3}, [%4];"
                 : "=r"(r0), "=r"(r1), "=r"(r2), "=r"(r3) : "r"(addr));
}

__device__ __forceinline__ void cpasync16(uint32_t dst, const void* src) {
    asm volatile("cp.async.cg.shared.global [%0], [%1], 16;" :: "r"(dst), "l"(src));
}

// ===================== gemmh: fp16 out-GEMM (128x128 tile, K-chunk 64, 3-stage, 2 CTA/SM) ====
#define HPITCH 144                 // 128B data + 16B pad
#define H_AB (128 * HPITCH)        // 18432 B per matrix per stage
#define HSTG (2 * H_AB)            // 36864 B per stage
#define HSMEM (3 * HSTG)           // 110592 B

__global__ void __launch_bounds__(256, 2) gemmh(
    const __half* __restrict__ Ag, const __half* __restrict__ Bg,
    float* __restrict__ C, const float* __restrict__ bias,
    int K, int lda, int ldb, int ldc)
{
    extern __shared__ char smc[];
    const uint32_t sb = (uint32_t)__cvta_generic_to_shared(smc);

    const int m0 = blockIdx.x * 128, n0 = blockIdx.y * 128;
    const int tid = threadIdx.x, lane = tid & 31, warp = tid >> 5;
    const int wm = (warp & 1) * 64, wn = (warp >> 1) * 32;
    const int gid = lane >> 2, tig = lane & 3;
    const int rsel = lane & 15, csel = (lane >> 4) * 16;
    const int KT = K >> 6;   // 64 k per stage

    float acc[4][4][4];
#pragma unroll
    for (int a = 0; a < 4; a++)
#pragma unroll
        for (int b = 0; b < 4; b++)
#pragma unroll
            for (int d = 0; d < 4; d++) acc[a][b][d] = 0.f;

#define HLOAD(KT_IDX, ST)                                                              \
    {                                                                                  \
        const int kof = (KT_IDX) * 64;                                                 \
        const uint32_t st = sb + (ST) * HSTG;                                          \
        _Pragma("unroll")                                                              \
        for (int i = 0; i < 4; i++) {                                                  \
            const int c = tid + 256 * i;                                               \
            const int row = c >> 3, off = c & 7;                                       \
            const uint32_t ad = st + row * HPITCH + off * 16;                          \
            cpasync16(ad,        Ag + (long long)(m0 + row) * lda + kof + off * 8);    \
            cpasync16(ad + H_AB, Bg + (long long)(n0 + row) * ldb + kof + off * 8);    \
        }                                                                              \
        asm volatile("cp.async.commit_group;");                                        \
    }

    HLOAD(0, 0);
    HLOAD(1, 1);

    for (int kt = 0; kt < KT; kt++) {
        if (kt + 2 < KT) asm volatile("cp.async.wait_group 1;");
        else             asm volatile("cp.async.wait_group 0;");
        __syncthreads();
        if (kt + 2 < KT) HLOAD(kt + 2, (kt + 2) % 3);

        const uint32_t base = sb + (kt % 3) * HSTG;
#pragma unroll
        for (int k16 = 0; k16 < 4; k16++) {
            const uint32_t kof = k16 * 32 + csel;
            uint32_t bh[4][2];
#pragma unroll
            for (int np = 0; np < 2; np++) {
                const uint32_t rb = base + H_AB + (wn + np * 16 + rsel) * HPITCH + kof;
                uint32_t t0, t1, t2, t3;
                ldsm4(t0, t1, t2, t3, rb);
                bh[2 * np][0] = t0; bh[2 * np][1] = t2;
                bh[2 * np + 1][0] = t1; bh[2 * np + 1][1] = t3;
            }
            uint32_t ah[4][4];
#pragma unroll
            for (int mf = 0; mf < 4; mf++) {
                const uint32_t ra = base + (wm + mf * 16 + rsel) * HPITCH + kof;
                ldsm4(ah[mf][0], ah[mf][1], ah[mf][2], ah[mf][3], ra);
            }
#pragma unroll
            for (int mf = 0; mf < 4; mf++)
#pragma unroll
                for (int nf = 0; nf < 4; nf++)
                    mma16h(acc[mf][nf], ah[mf], bh[nf]);
        }
    }

#pragma unroll
    for (int mf = 0; mf < 4; mf++) {
        const int r = m0 + wm + mf * 16 + gid;
#pragma unroll
        for (int nf = 0; nf < 4; nf++) {
            const int c = n0 + wn + nf * 8 + 2 * tig;
            float b0 = bias[c], b1 = bias[c + 1];
            float2 v0 = {acc[mf][nf][0] + b0, acc[mf][nf][1] + b1};
            float2 v1 = {acc[mf][nf][2] + b0, acc[mf][nf][3] + b1};
            *(float2*)&C[(long long)r * ldc + c] = v0;
            *(float2*)&C[(long long)(r + 8) * ldc + c] = v1;
        }
    }
}

// ===================== gemmb: bf16 3-term (small/batched GEMMs) =====
#define PITCH 80
#define MAT_B (128 * PITCH)
#define STG_B (4 * MAT_B)

__global__ void __launch_bounds__(256, 2) gemmb(
    const __nv_bfloat16* __restrict__ Ahg, const __nv_bfloat16* __restrict__ Alg,
    const __nv_bfloat16* __restrict__ Bhg, const __nv_bfloat16* __restrict__ Blg,
    float* __restrict__ C, const float* __restrict__ bias,
    int K, int lda, int ldb, int ldc,
    long long sA, long long sB, long long sC, float alpha)
{
    extern __shared__ char smc[];
    const uint32_t sb = (uint32_t)__cvta_generic_to_shared(smc);

    Ahg += sA * blockIdx.z; Alg += sA * blockIdx.z;
    Bhg += sB * blockIdx.z; Blg += sB * blockIdx.z;
    C += sC * blockIdx.z;

    const int m0 = blockIdx.x * 128, n0 = blockIdx.y * 128;
    const int tid = threadIdx.x, lane = tid & 31, warp = tid >> 5;
    const int wm = (warp & 1) * 64, wn = (warp >> 1) * 32;
    const int gid = lane >> 2, tig = lane & 3;
    const int rsel = lane & 15, csel = (lane >> 4) * 16;
    const int KT = K >> 5;
    const int lrow = tid >> 2, loff = tid & 3;

    float acc[4][4][4];
#pragma unroll
    for (int a = 0; a < 4; a++)
#pragma unroll
        for (int b = 0; b < 4; b++)
#pragma unroll
            for (int d = 0; d < 4; d++) acc[a][b][d] = 0.f;

#define LOAD_STAGE(KT_IDX, ST)                                                          \
    {                                                                                   \
        const int kofs = (KT_IDX) * 32 + loff * 8;                                      \
        const uint32_t db = sb + (ST) * STG_B + lrow * PITCH + loff * 16;               \
        cpasync16(db,                  Ahg + (long long)(m0 + lrow) * lda + kofs);      \
        cpasync16(db + 64 * PITCH,     Ahg + (long long)(m0 + lrow + 64) * lda + kofs); \
        cpasync16(db + MAT_B,          Alg + (long long)(m0 + lrow) * lda + kofs);      \
        cpasync16(db + MAT_B + 64 * PITCH, Alg + (long long)(m0 + lrow + 64) * lda + kofs); \
        cpasync16(db + 2 * MAT_B,      Bhg + (long long)(n0 + lrow) * ldb + kofs);      \
        cpasync16(db + 2 * MAT_B + 64 * PITCH, Bhg + (long long)(n0 + lrow + 64) * ldb + kofs); \
        cpasync16(db + 3 * MAT_B,      Blg + (long long)(n0 + lrow) * ldb + kofs);      \
        cpasync16(db + 3 * MAT_B + 64 * PITCH, Blg + (long long)(n0 + lrow + 64) * ldb + kofs); \
        asm volatile("cp.async.commit_group;");                                         \
    }

    LOAD_STAGE(0, 0);

    for (int kt = 0; kt < KT; kt++) {
        if (kt + 1 < KT) {
            LOAD_STAGE(kt + 1, (kt + 1) & 1);
            asm volatile("cp.async.wait_group 1;");
        } else {
            asm volatile("cp.async.wait_group 0;");
        }
        __syncthreads();

        const uint32_t base = sb + (kt & 1) * STG_B;
#pragma unroll
        for (int k16 = 0; k16 < 2; k16++) {
            const uint32_t kof = k16 * 32 + csel;
            uint32_t bh[4][2], bl[4][2];
#pragma unroll
            for (int np = 0; np < 2; np++) {
                const uint32_t rb = base + 2 * MAT_B + (wn + np * 16 + rsel) * PITCH + kof;
                uint32_t t0, t1, t2, t3;
                ldsm4(t0, t1, t2, t3, rb);
                bh[2 * np][0] = t0; bh[2 * np][1] = t2;
                bh[2 * np + 1][0] = t1; bh[2 * np + 1][1] = t3;
                ldsm4(t0, t1, t2, t3, rb + MAT_B);
                bl[2 * np][0] = t0; bl[2 * np][1] = t2;
                bl[2 * np + 1][0] = t1; bl[2 * np + 1][1] = t3;
            }
#pragma unroll
            for (int mg = 0; mg < 2; mg++) {
                uint32_t ah[2][4], al[2][4];
#pragma unroll
                for (int mi = 0; mi < 2; mi++) {
                    const uint32_t ra = base + (wm + (mg * 2 + mi) * 16 + rsel) * PITCH + kof;
                    ldsm4(ah[mi][0], ah[mi][1], ah[mi][2], ah[mi][3], ra);
                    ldsm4(al[mi][0], al[mi][1], al[mi][2], al[mi][3], ra + MAT_B);
                }
#pragma unroll
                for (int mi = 0; mi < 2; mi++)
#pragma unroll
                    for (int nf = 0; nf < 4; nf++)
                        mma16b(acc[mg * 2 + mi][nf], ah[mi], bh[nf]);
#pragma unroll
                for (int mi = 0; mi < 2; mi++)
#pragma unroll
                    for (int nf = 0; nf < 4; nf++)
                        mma16b(acc[mg * 2 + mi][nf], ah[mi], bl[nf]);
#pragma unroll
                for (int mi = 0; mi < 2; mi++)
#pragma unroll
                    for (int nf = 0; nf < 4; nf++)
                        mma16b(acc[mg * 2 + mi][nf], al[mi], bh[nf]);
            }
        }
        __syncthreads();
    }

#pragma unroll
    for (int mf = 0; mf < 4; mf++) {
        const int r = m0 + wm + mf * 16 + gid;
#pragma unroll
        for (int nf = 0; nf < 4; nf++) {
            const int c = n0 + wn + nf * 8 + 2 * tig;
            float b0 = bias ? bias[c] : 0.f;
            float b1 = bias ? bias[c + 1] : 0.f;
            float2 v0 = {alpha * acc[mf][nf][0] + b0, alpha * acc[mf][nf][1] + b1};
            float2 v1 = {alpha * acc[mf][nf][2] + b0, alpha * acc[mf][nf][3] + b1};
            *(float2*)&C[(long long)r * ldc + c] = v0;
            *(float2*)&C[(long long)(r + 8) * ldc + c] = v1;
        }
    }
}

// ===================== split / convert kernels =====================
__global__ void k_split(const float4* __restrict__ in, __nv_bfloat162* __restrict__ hi,
                        __nv_bfloat162* __restrict__ lo, int n4) {
    int i = blockIdx.x * 256 + threadIdx.x;
    if (i >= n4) return;
    float4 v = in[i];
    __nv_bfloat16 h0 = __float2bfloat16(v.x), h1 = __float2bfloat16(v.y);
    __nv_bfloat16 h2 = __float2bfloat16(v.z), h3 = __float2bfloat16(v.w);
    hi[2 * i]     = __nv_bfloat162(h0, h1);
    hi[2 * i + 1] = __nv_bfloat162(h2, h3);
    lo[2 * i]     = __nv_bfloat162(__float2bfloat16(v.x - __bfloat162float(h0)),
                                   __float2bfloat16(v.y - __bfloat162float(h1)));
    lo[2 * i + 1] = __nv_bfloat162(__float2bfloat16(v.z - __bfloat162float(h2)),
                                   __float2bfloat16(v.w - __bfloat162float(h3)));
}

__global__ void k_half(const float4* __restrict__ in, __half2* __restrict__ out, int n4) {
    int i = blockIdx.x * 256 + threadIdx.x;
    if (i >= n4) return;
    float4 v = in[i];
    out[2 * i]     = __half2(__float2half_rn(v.x), __float2half_rn(v.y));
    out[2 * i + 1] = __half2(__float2half_rn(v.z), __float2half_rn(v.w));
}

// ===================== consolidated init =====================
__global__ void k_init(const int* __restrict__ y, const float* __restrict__ tab,
                       const float4* __restrict__ Wih,
                       const float* __restrict__ bih, const float* __restrict__ bhh) {
    const int bk = blockIdx.x, tid = threadIdx.x;
    if (bk < 512) {  // emb gather + bf16 split
        int i = bk * 256 + tid;
        int bs = i >> 6, e = i & 63;
        float4 v = ((const float4*)(tab + (long long)y[bs] * 256))[e];
        __nv_bfloat16 h0 = __float2bfloat16(v.x), h1 = __float2bfloat16(v.y);
        __nv_bfloat16 h2 = __float2bfloat16(v.z), h3 = __float2bfloat16(v.w);
        ((__nv_bfloat162*)s_emb_h)[2 * i]     = __nv_bfloat162(h0, h1);
        ((__nv_bfloat162*)s_emb_h)[2 * i + 1] = __nv_bfloat162(h2, h3);
        ((__nv_bfloat162*)s_emb_l)[2 * i]     = __nv_bfloat162(__float2bfloat16(v.x - __bfloat162float(h0)),
                                                               __float2bfloat16(v.y - __bfloat162float(h1)));
        ((__nv_bfloat162*)s_emb_l)[2 * i + 1] = __nv_bfloat162(__float2bfloat16(v.z - __bfloat162float(h2)),
                                                               __float2bfloat16(v.w - __bfloat162float(h3)));
    } else if (bk < 1024) {  // Wih bf16 split
        int i = (bk - 512) * 256 + tid;
        float4 v = Wih[i];
        __nv_bfloat16 h0 = __float2bfloat16(v.x), h1 = __float2bfloat16(v.y);
        __nv_bfloat16 h2 = __float2bfloat16(v.z), h3 = __float2bfloat16(v.w);
        ((__nv_bfloat162*)s_wih_h)[2 * i]     = __nv_bfloat162(h0, h1);
        ((__nv_bfloat162*)s_wih_h)[2 * i + 1] = __nv_bfloat162(h2, h3);
        ((__nv_bfloat162*)s_wih_l)[2 * i]     = __nv_bfloat162(__float2bfloat16(v.x - __bfloat162float(h0)),
                                                               __float2bfloat16(v.y - __bfloat162float(h1)));
        ((__nv_bfloat162*)s_wih_l)[2 * i + 1] = __nv_bfloat162(__float2bfloat16(v.z - __bfloat162float(h2)),
                                                               __float2bfloat16(v.w - __bfloat162float(h3)));
    } else {  // biases, h state, barrier
        int i = (bk - 1024) * 256 + tid;
        if (i < 2048) g_bcomb[i] = bih[i] + bhh[i];
        if (i < 8192) g_hbuf[i] = 0.f;
        if (i == 0) g_bar = 0;
    }
}

__global__ void k_transpose(const float* __restrict__ in, float* __restrict__ out, int R, int C) {
    __shared__ float t[32][33];
    in += (long long)blockIdx.z * R * C;
    out += (long long)blockIdx.z * R * C;
    int c0 = blockIdx.x * 32, r0 = blockIdx.y * 32;
    int x = threadIdx.x, y = threadIdx.y;
#pragma unroll
    for (int i = 0; i < 32; i += 8)
        if (r0 + y + i < R && c0 + x < C) t[y + i][x] = in[(r0 + y + i) * C + c0 + x];
    __syncthreads();
#pragma unroll
    for (int i = 0; i < 32; i += 8)
        if (c0 + y + i < C && r0 + x < R) out[(c0 + y + i) * R + r0 + x] = t[x][y + i];
}

// softmax: writes probs directly as bf16 hi/lo
__global__ void k_softmax(const uint32_t* __restrict__ mask) {
    int w = (blockIdx.x * blockDim.x + threadIdx.x) >> 5;
    int lane = threadIdx.x & 31;
    if (w >= 2048) return;
    int b = w >> 7;
    const float* row = g_scores + w * 128;
    const uint32_t* m = mask + b * 128;
    float v[4];
    float mx = -1e30f;
#pragma unroll
    for (int i = 0; i < 4; i++) {
        int l = lane + 32 * i;
        v[i] = (m[l] != 0u) ? row[l] : -1e9f;
        mx = fmaxf(mx, v[i]);
    }
#pragma unroll
    for (int o = 16; o > 0; o >>= 1) mx = fmaxf(mx, __shfl_xor_sync(0xffffffffu, mx, o));
    float s = 0.f;
#pragma unroll
    for (int i = 0; i < 4; i++) { v[i] = expf(v[i] - mx); s += v[i]; }
#pragma unroll
    for (int o = 16; o > 0; o >>= 1) s += __shfl_xor_sync(0xffffffffu, s, o);
    float inv = 1.f / s;
#pragma unroll
    for (int i = 0; i < 4; i++) {
        float p = v[i] * inv;
        __nv_bfloat16 h = __float2bfloat16(p);
        int idx = w * 128 + lane + 32 * i;
        s_sc_h[idx] = h;
        s_sc_l[idx] = __float2bfloat16(p - __bfloat162float(h));
    }
}

// ===================== persistent LSTM (W in smem) + fused W_out fp16 convert ========
__device__ __forceinline__ void gridbar(unsigned target) {
    __syncthreads();
    if (threadIdx.x == 0) {
        __threadfence();
        atomicAdd(&g_bar, 1);
        while (*(volatile unsigned*)&g_bar < target) __nanosleep(32);
        __threadfence();
    }
    __syncthreads();
}

#define SPLIT_BLOCKS 256
#define LSTM_SMEM ((8192 + 8192 + 4096 + 256) * 4)   // w_sm + h_sm + red + sgate = 82944 B

__global__ void __launch_bounds__(256) lstm_kernel(
    const float* __restrict__ xw,
    const float4* __restrict__ wout, __half2* __restrict__ wo16)
{
    const int tid = threadIdx.x, bk = blockIdx.x;

    if (bk >= 128) {  // W_out -> fp16 converter
        for (int i = (bk - 128) * 256 + tid; i < 8192000; i += SPLIT_BLOCKS * 256) {
            float4 v = wout[i];
            wo16[2 * i]     = __half2(__float2half_rn(v.x), __float2half_rn(v.y));
            wo16[2 * i + 1] = __half2(__float2half_rn(v.z), __float2half_rn(v.w));
        }
        return;
    }

    extern __shared__ float smf[];
    float* w_sm = smf;                 // [512][16]: w_sm[k*16 + g*4 + jj]
    float* h_sm = smf + 8192;          // [512][16]: h_sm[k*16 + b]
    float* red = smf + 16384;          // [16ks][16j][16b]
    float* sgate = smf + 20480;        // [16j][16b]

    const int u0 = bk * 4;

    // Load W_hh slice into smem ONCE (immune to per-step L1 flush)
    for (int i = tid; i < 2048; i += 256) {
        int k = i >> 2, g = i & 3;
        ((float4*)w_sm)[k * 4 + g] = *(const float4*)(g_whhT + k * 2048 + g * 512 + u0);
    }

    const int ks = tid >> 4;
    const int bg = (tid >> 2) & 3;
    const int jg = tid & 3;
    const int b0 = bg * 4;
    const int rj = tid >> 4, rb = tid & 15;
    const int puu = tid >> 4, pbb = tid & 15;
    float creg = 0.f;

    // xw pointer for the reduce-phase thread; prefetch step 0
    const int gx = rj >> 2, uux = rj & 3;
    const float* xwp = xw + (long long)(rb * 128) * 2048 + gx * 512 + u0 + uux;
    float xw_cur = xwp[0];
    __syncthreads();

    for (int t = 0; t < 128; t++) {
        // h broadcast (32KB from L2)
#pragma unroll
        for (int i = tid; i < 2048; i += 256)
            ((float4*)h_sm)[i] = ((const float4*)g_hbuf)[i];
        __syncthreads();

        float a[4][4];
#pragma unroll
        for (int jj = 0; jj < 4; jj++)
#pragma unroll
            for (int bb = 0; bb < 4; bb++) a[jj][bb] = 0.f;

        const float* wp = w_sm + (ks * 32) * 16 + jg * 4;
        const float* hp = h_sm + (ks * 32) * 16 + b0;
#pragma unroll 8
        for (int k = 0; k < 32; k++) {
            float4 wv = *(const float4*)wp;
            float4 hv = *(const float4*)hp;
            wp += 16; hp += 16;
            float wa[4] = {wv.x, wv.y, wv.z, wv.w};
            float ha[4] = {hv.x, hv.y, hv.z, hv.w};
#pragma unroll
            for (int jj = 0; jj < 4; jj++)
#pragma unroll
                for (int bb = 0; bb < 4; bb++) a[jj][bb] = fmaf(wa[jj], ha[bb], a[jj][bb]);
        }
#pragma unroll
        for (int jj = 0; jj < 4; jj++)
#pragma unroll
            for (int bb = 0; bb < 4; bb++)
                red[ks * 256 + (jg * 4 + jj) * 16 + (bg * 4 + bb)] = a[jj][bb];
        __syncthreads();

        float s = 0.f;
#pragma unroll
        for (int q = 0; q < 16; q++) s += red[q * 256 + rj * 16 + rb];
        s += xw_cur;
        sgate[rj * 16 + rb] = s;
        __syncthreads();

        if (tid < 64) {
            float gi = sgate[(0 * 4 + puu) * 16 + pbb];
            float gf = sgate[(1 * 4 + puu) * 16 + pbb];
            float gg = sgate[(2 * 4 + puu) * 16 + pbb];
            float go = sgate[(3 * 4 + puu) * 16 + pbb];
            creg = sigm(gf) * creg + sigm(gi) * tanhf(gg);
            float h = sigm(go) * tanhf(creg);
            g_hbuf[(u0 + puu) * 16 + pbb] = h;
            g_cat[(pbb * 128 + t) * 1024 + u0 + puu] = h;
        }
        // prefetch next step's xw before the barrier (hides post-flush L2 latency)
        if (t + 1 < 128) xw_cur = xwp[(t + 1) * 2048];
        gridbar(128u * (t + 1));
    }
}

// ===================== host launcher =====================
extern "C" void kernel_launch(void* const* d_in, const int* in_sizes, int n_in,
                              void* d_out, int out_size) {
    const int* y = (const int*)d_in[0];
    const float* tab = (const float*)d_in[1];
    const float* Wih = (const float*)d_in[2];
    const float* Whh = (const float*)d_in[3];
    const float* bih = (const float*)d_in[4];
    const float* bhh = (const float*)d_in[5];
    const float* enc = (const float*)d_in[6];
    const uint32_t* mask = (const uint32_t*)d_in[7];
    const float* Wout = (const float*)d_in[8];
    const float* bout = (const float*)d_in[9];
    float* out = (float*)d_out;

    float *p_xw, *p_cat, *p_scores, *p_encT, *p_whhT, *p_bcomb;
    cudaGetSymbolAddress((void**)&p_xw, g_xw);
    cudaGetSymbolAddress((void**)&p_cat, g_cat);
    cudaGetSymbolAddress((void**)&p_scores, g_scores);
    cudaGetSymbolAddress((void**)&p_encT, g_encT);
    cudaGetSymbolAddress((void**)&p_whhT, g_whhT);
    cudaGetSymbolAddress((void**)&p_bcomb, g_bcomb);

    __nv_bfloat16 *e_h, *e_l, *wi_h, *wi_l, *c_h, *c_l;
    __nv_bfloat16 *en_h, *en_l, *et_h, *et_l, *sc_h, *sc_l;
    cudaGetSymbolAddress((void**)&e_h, s_emb_h);   cudaGetSymbolAddress((void**)&e_l, s_emb_l);
    cudaGetSymbolAddress((void**)&wi_h, s_wih_h);  cudaGetSymbolAddress((void**)&wi_l, s_wih_l);
    cudaGetSymbolAddress((void**)&c_h, s_cat_h);   cudaGetSymbolAddress((void**)&c_l, s_cat_l);
    cudaGetSymbolAddress((void**)&en_h, s_enc_h);  cudaGetSymbolAddress((void**)&en_l, s_enc_l);
    cudaGetSymbolAddress((void**)&et_h, s_encT_h); cudaGetSymbolAddress((void**)&et_l, s_encT_l);
    cudaGetSymbolAddress((void**)&sc_h, s_sc_h);   cudaGetSymbolAddress((void**)&sc_l, s_sc_l);

    __half *c16, *wo16;
    cudaGetSymbolAddress((void**)&c16, s_cat16);
    cudaGetSymbolAddress((void**)&wo16, s_wout16);

    cudaFuncSetAttribute(gemmb, cudaFuncAttributeMaxDynamicSharedMemorySize, 2 * STG_B);
    cudaFuncSetAttribute(gemmh, cudaFuncAttributeMaxDynamicSharedMemorySize, HSMEM);
    cudaFuncSetAttribute(lstm_kernel, cudaFuncAttributeMaxDynamicSharedMemorySize, LSTM_SMEM);

    // #1: consolidated init
    k_init<<<1056, 256>>>(y, tab, (const float4*)Wih, bih, bhh);

    // #2: xw = emb @ W_ih^T + (b_ih + b_hh)   [bf16 3-term]
    gemmb<<<dim3(16, 16, 1), 256, 2 * STG_B>>>(e_h, e_l, wi_h, wi_l, p_xw, p_bcomb,
                                               256, 256, 256, 2048, 0, 0, 0, 1.f);

    // #3: W_hh transpose
    k_transpose<<<dim3(16, 64, 1), dim3(32, 8)>>>(Whh, p_whhT, 2048, 512);

    // #4: LSTM + fused W_out fp16 conversion   <-- ncu-profiled launch
    lstm_kernel<<<128 + SPLIT_BLOCKS, 256, LSTM_SMEM>>>(p_xw, (const float4*)Wout, (__half2*)wo16);

    // enc prep
    k_transpose<<<dim3(16, 4, 16), dim3(32, 8)>>>(enc, p_encT, 128, 512);
    k_split<<<1024, 256>>>((const float4*)enc, (__nv_bfloat162*)en_h, (__nv_bfloat162*)en_l, 262144);
    k_split<<<1024, 256>>>((const float4*)p_encT, (__nv_bfloat162*)et_h, (__nv_bfloat162*)et_l, 262144);

    k_split<<<2048, 256>>>((const float4*)p_cat, (__nv_bfloat162*)c_h, (__nv_bfloat162*)c_l, 524288);

    // scores = dec @ enc^T / sqrt(H)        [bf16 3-term]
    gemmb<<<dim3(1, 1, 16), 256, 2 * STG_B>>>(c_h, c_l, en_h, en_l, p_scores, nullptr,
                                              512, 1024, 512, 128,
                                              131072LL, 65536LL, 16384LL,
                                              0.044194173824159216f);
    k_softmax<<<256, 256>>>(mask);

    // context = probs @ enc                 [bf16 3-term]
    gemmb<<<dim3(1, 4, 16), 256, 2 * STG_B>>>(sc_h, sc_l, et_h, et_l, p_cat + 512, nullptr,
                                              128, 128, 128, 1024,
                                              16384LL, 65536LL, 131072LL, 1.f);

    // cat -> fp16
    k_half<<<2048, 256>>>((const float4*)p_cat, (__half2*)c16, 524288);

    // logits = cat @ W_out^T + b_out        [fp16 1-term]
    gemmh<<<dim3(16, 250), 256, HSMEM>>>(c16, wo16, out, bout, 1024, 1024, 1024, 32000);
}

// round 13
// speedup vs baseline: 1.5450x; 1.1466x over previous
#include <cuda_runtime.h>
#include <cuda_bf16.h>
#include <cuda_fp16.h>
#include <cstdint>

// ===================== device scratch (static, no allocation) =====================
__device__ __align__(16) float g_xw[2048 * 2048];
__device__ __align__(16) float g_cat[2048 * 1024];
__device__ __align__(16) float g_scores[16 * 128 * 128];
__device__ __align__(16) float g_encT[16 * 512 * 128];
__device__ __align__(16) float g_whhT[512 * 2048];
__device__ __align__(16) float g_hbuf[512 * 16];
__device__ __align__(16) float g_bcomb[2048];
__device__ unsigned g_bar;

// bf16 3-term operands (small GEMMs)
__device__ __align__(16) __nv_bfloat16 s_emb_h[2048 * 256],  s_emb_l[2048 * 256];
__device__ __align__(16) __nv_bfloat16 s_wih_h[2048 * 256],  s_wih_l[2048 * 256];
__device__ __align__(16) __nv_bfloat16 s_cat_h[2048 * 1024], s_cat_l[2048 * 1024];
__device__ __align__(16) __nv_bfloat16 s_enc_h[16 * 128 * 512], s_enc_l[16 * 128 * 512];
__device__ __align__(16) __nv_bfloat16 s_encT_h[16 * 512 * 128], s_encT_l[16 * 512 * 128];
__device__ __align__(16) __nv_bfloat16 s_sc_h[16 * 128 * 128], s_sc_l[16 * 128 * 128];

// fp16 operands (output projection)
__device__ __align__(16) __half s_cat16[2048 * 1024];
__device__ __align__(16) __half s_wout16[32000 * 1024];

// ===================== helpers =====================
__device__ __forceinline__ float sigm(float x) { return 1.f / (1.f + expf(-x)); }

__device__ __forceinline__ void mma16b(float* d, const uint32_t* a, const uint32_t* b) {
    asm volatile(
        "mma.sync.aligned.m16n8k16.row.col.f32.bf16.bf16.f32 "
        "{%0,%1,%2,%3}, {%4,%5,%6,%7}, {%8,%9}, {%0,%1,%2,%3};"
        : "+f"(d[0]), "+f"(d[1]), "+f"(d[2]), "+f"(d[3])
        : "r"(a[0]), "r"(a[1]), "r"(a[2]), "r"(a[3]), "r"(b[0]), "r"(b[1]));
}

__device__ __forceinline__ void mma16h(float* d, const uint32_t* a, const uint32_t* b) {
    asm volatile(
        "mma.sync.aligned.m16n8k16.row.col.f32.f16.f16.f32 "
        "{%0,%1,%2,%3}, {%4,%5,%6,%7}, {%8,%9}, {%0,%1,%2,%3};"
        : "+f"(d[0]), "+f"(d[1]), "+f"(d[2]), "+f"(d[3])
        : "r"(a[0]), "r"(a[1]), "r"(a[2]), "r"(a[3]), "r"(b[0]), "r"(b[1]));
}

__device__ __forceinline__ void ldsm4(uint32_t& r0, uint32_t& r1, uint32_t& r2, uint32_t& r3,
                                      uint32_t addr) {
    asm volatile("ldmatrix.sync.aligned.m8n8.x4.shared.b16 {%0,%1,%2,%3}, [%4];"
                 : "=r"(r0), "=r"(r1), "=r"(r2), "=r"(r3) : "r"(addr));
}

__device__ __forceinline__ void cpasync16(uint32_t dst, const void* src) {
    asm volatile("cp.async.cg.shared.global [%0], [%1], 16;" :: "r"(dst), "l"(src));
}

// ===================== gemmh: fp16 out-GEMM (128x128 tile, K-chunk 64, 3-stage, 2 CTA/SM) ====
#define HPITCH 144
#define H_AB (128 * HPITCH)
#define HSTG (2 * H_AB)
#define HSMEM (3 * HSTG)

__global__ void __launch_bounds__(256, 2) gemmh(
    const __half* __restrict__ Ag, const __half* __restrict__ Bg,
    float* __restrict__ C, const float* __restrict__ bias,
    int K, int lda, int ldb, int ldc)
{
    extern __shared__ char smc[];
    const uint32_t sb = (uint32_t)__cvta_generic_to_shared(smc);

    const int m0 = blockIdx.x * 128, n0 = blockIdx.y * 128;
    const int tid = threadIdx.x, lane = tid & 31, warp = tid >> 5;
    const int wm = (warp & 1) * 64, wn = (warp >> 1) * 32;
    const int gid = lane >> 2, tig = lane & 3;
    const int rsel = lane & 15, csel = (lane >> 4) * 16;
    const int KT = K >> 6;

    float acc[4][4][4];
#pragma unroll
    for (int a = 0; a < 4; a++)
#pragma unroll
        for (int b = 0; b < 4; b++)
#pragma unroll
            for (int d = 0; d < 4; d++) acc[a][b][d] = 0.f;

#define HLOAD(KT_IDX, ST)                                                              \
    {                                                                                  \
        const int kof = (KT_IDX) * 64;                                                 \
        const uint32_t st = sb + (ST) * HSTG;                                          \
        _Pragma("unroll")                                                              \
        for (int i = 0; i < 4; i++) {                                                  \
            const int c = tid + 256 * i;                                               \
            const int row = c >> 3, off = c & 7;                                       \
            const uint32_t ad = st + row * HPITCH + off * 16;                          \
            cpasync16(ad,        Ag + (long long)(m0 + row) * lda + kof + off * 8);    \
            cpasync16(ad + H_AB, Bg + (long long)(n0 + row) * ldb + kof + off * 8);    \
        }                                                                              \
        asm volatile("cp.async.commit_group;");                                        \
    }

    HLOAD(0, 0);
    HLOAD(1, 1);

    for (int kt = 0; kt < KT; kt++) {
        if (kt + 2 < KT) asm volatile("cp.async.wait_group 1;");
        else             asm volatile("cp.async.wait_group 0;");
        __syncthreads();
        if (kt + 2 < KT) HLOAD(kt + 2, (kt + 2) % 3);

        const uint32_t base = sb + (kt % 3) * HSTG;
#pragma unroll
        for (int k16 = 0; k16 < 4; k16++) {
            const uint32_t kof = k16 * 32 + csel;
            uint32_t bh[4][2];
#pragma unroll
            for (int np = 0; np < 2; np++) {
                const uint32_t rb = base + H_AB + (wn + np * 16 + rsel) * HPITCH + kof;
                uint32_t t0, t1, t2, t3;
                ldsm4(t0, t1, t2, t3, rb);
                bh[2 * np][0] = t0; bh[2 * np][1] = t2;
                bh[2 * np + 1][0] = t1; bh[2 * np + 1][1] = t3;
            }
            uint32_t ah[4][4];
#pragma unroll
            for (int mf = 0; mf < 4; mf++) {
                const uint32_t ra = base + (wm + mf * 16 + rsel) * HPITCH + kof;
                ldsm4(ah[mf][0], ah[mf][1], ah[mf][2], ah[mf][3], ra);
            }
#pragma unroll
            for (int mf = 0; mf < 4; mf++)
#pragma unroll
                for (int nf = 0; nf < 4; nf++)
                    mma16h(acc[mf][nf], ah[mf], bh[nf]);
        }
    }

#pragma unroll
    for (int mf = 0; mf < 4; mf++) {
        const int r = m0 + wm + mf * 16 + gid;
#pragma unroll
        for (int nf = 0; nf < 4; nf++) {
            const int c = n0 + wn + nf * 8 + 2 * tig;
            float b0 = bias[c], b1 = bias[c + 1];
            float2 v0 = {acc[mf][nf][0] + b0, acc[mf][nf][1] + b1};
            float2 v1 = {acc[mf][nf][2] + b0, acc[mf][nf][3] + b1};
            *(float2*)&C[(long long)r * ldc + c] = v0;
            *(float2*)&C[(long long)(r + 8) * ldc + c] = v1;
        }
    }
}

// ===================== gemmb: bf16 3-term (small/batched GEMMs) =====
#define PITCH 80
#define MAT_B (128 * PITCH)
#define STG_B (4 * MAT_B)

__global__ void __launch_bounds__(256, 2) gemmb(
    const __nv_bfloat16* __restrict__ Ahg, const __nv_bfloat16* __restrict__ Alg,
    const __nv_bfloat16* __restrict__ Bhg, const __nv_bfloat16* __restrict__ Blg,
    float* __restrict__ C, const float* __restrict__ bias,
    int K, int lda, int ldb, int ldc,
    long long sA, long long sB, long long sC, float alpha)
{
    extern __shared__ char smc[];
    const uint32_t sb = (uint32_t)__cvta_generic_to_shared(smc);

    Ahg += sA * blockIdx.z; Alg += sA * blockIdx.z;
    Bhg += sB * blockIdx.z; Blg += sB * blockIdx.z;
    C += sC * blockIdx.z;

    const int m0 = blockIdx.x * 128, n0 = blockIdx.y * 128;
    const int tid = threadIdx.x, lane = tid & 31, warp = tid >> 5;
    const int wm = (warp & 1) * 64, wn = (warp >> 1) * 32;
    const int gid = lane >> 2, tig = lane & 3;
    const int rsel = lane & 15, csel = (lane >> 4) * 16;
    const int KT = K >> 5;
    const int lrow = tid >> 2, loff = tid & 3;

    float acc[4][4][4];
#pragma unroll
    for (int a = 0; a < 4; a++)
#pragma unroll
        for (int b = 0; b < 4; b++)
#pragma unroll
            for (int d = 0; d < 4; d++) acc[a][b][d] = 0.f;

#define LOAD_STAGE(KT_IDX, ST)                                                          \
    {                                                                                   \
        const int kofs = (KT_IDX) * 32 + loff * 8;                                      \
        const uint32_t db = sb + (ST) * STG_B + lrow * PITCH + loff * 16;               \
        cpasync16(db,                  Ahg + (long long)(m0 + lrow) * lda + kofs);      \
        cpasync16(db + 64 * PITCH,     Ahg + (long long)(m0 + lrow + 64) * lda + kofs); \
        cpasync16(db + MAT_B,          Alg + (long long)(m0 + lrow) * lda + kofs);      \
        cpasync16(db + MAT_B + 64 * PITCH, Alg + (long long)(m0 + lrow + 64) * lda + kofs); \
        cpasync16(db + 2 * MAT_B,      Bhg + (long long)(n0 + lrow) * ldb + kofs);      \
        cpasync16(db + 2 * MAT_B + 64 * PITCH, Bhg + (long long)(n0 + lrow + 64) * ldb + kofs); \
        cpasync16(db + 3 * MAT_B,      Blg + (long long)(n0 + lrow) * ldb + kofs);      \
        cpasync16(db + 3 * MAT_B + 64 * PITCH, Blg + (long long)(n0 + lrow + 64) * ldb + kofs); \
        asm volatile("cp.async.commit_group;");                                         \
    }

    LOAD_STAGE(0, 0);

    for (int kt = 0; kt < KT; kt++) {
        if (kt + 1 < KT) {
            LOAD_STAGE(kt + 1, (kt + 1) & 1);
            asm volatile("cp.async.wait_group 1;");
        } else {
            asm volatile("cp.async.wait_group 0;");
        }
        __syncthreads();

        const uint32_t base = sb + (kt & 1) * STG_B;
#pragma unroll
        for (int k16 = 0; k16 < 2; k16++) {
            const uint32_t kof = k16 * 32 + csel;
            uint32_t bh[4][2], bl[4][2];
#pragma unroll
            for (int np = 0; np < 2; np++) {
                const uint32_t rb = base + 2 * MAT_B + (wn + np * 16 + rsel) * PITCH + kof;
                uint32_t t0, t1, t2, t3;
                ldsm4(t0, t1, t2, t3, rb);
                bh[2 * np][0] = t0; bh[2 * np][1] = t2;
                bh[2 * np + 1][0] = t1; bh[2 * np + 1][1] = t3;
                ldsm4(t0, t1, t2, t3, rb + MAT_B);
                bl[2 * np][0] = t0; bl[2 * np][1] = t2;
                bl[2 * np + 1][0] = t1; bl[2 * np + 1][1] = t3;
            }
#pragma unroll
            for (int mg = 0; mg < 2; mg++) {
                uint32_t ah[2][4], al[2][4];
#pragma unroll
                for (int mi = 0; mi < 2; mi++) {
                    const uint32_t ra = base + (wm + (mg * 2 + mi) * 16 + rsel) * PITCH + kof;
                    ldsm4(ah[mi][0], ah[mi][1], ah[mi][2], ah[mi][3], ra);
                    ldsm4(al[mi][0], al[mi][1], al[mi][2], al[mi][3], ra + MAT_B);
                }
#pragma unroll
                for (int mi = 0; mi < 2; mi++)
#pragma unroll
                    for (int nf = 0; nf < 4; nf++)
                        mma16b(acc[mg * 2 + mi][nf], ah[mi], bh[nf]);
#pragma unroll
                for (int mi = 0; mi < 2; mi++)
#pragma unroll
                    for (int nf = 0; nf < 4; nf++)
                        mma16b(acc[mg * 2 + mi][nf], ah[mi], bl[nf]);
#pragma unroll
                for (int mi = 0; mi < 2; mi++)
#pragma unroll
                    for (int nf = 0; nf < 4; nf++)
                        mma16b(acc[mg * 2 + mi][nf], al[mi], bh[nf]);
            }
        }
        __syncthreads();
    }

#pragma unroll
    for (int mf = 0; mf < 4; mf++) {
        const int r = m0 + wm + mf * 16 + gid;
#pragma unroll
        for (int nf = 0; nf < 4; nf++) {
            const int c = n0 + wn + nf * 8 + 2 * tig;
            float b0 = bias ? bias[c] : 0.f;
            float b1 = bias ? bias[c + 1] : 0.f;
            float2 v0 = {alpha * acc[mf][nf][0] + b0, alpha * acc[mf][nf][1] + b1};
            float2 v1 = {alpha * acc[mf][nf][2] + b0, alpha * acc[mf][nf][3] + b1};
            *(float2*)&C[(long long)r * ldc + c] = v0;
            *(float2*)&C[(long long)(r + 8) * ldc + c] = v1;
        }
    }
}

// ===================== split / convert kernels =====================
__global__ void k_split(const float4* __restrict__ in, __nv_bfloat162* __restrict__ hi,
                        __nv_bfloat162* __restrict__ lo, int n4) {
    int i = blockIdx.x * 256 + threadIdx.x;
    if (i >= n4) return;
    float4 v = in[i];
    __nv_bfloat16 h0 = __float2bfloat16(v.x), h1 = __float2bfloat16(v.y);
    __nv_bfloat16 h2 = __float2bfloat16(v.z), h3 = __float2bfloat16(v.w);
    hi[2 * i]     = __nv_bfloat162(h0, h1);
    hi[2 * i + 1] = __nv_bfloat162(h2, h3);
    lo[2 * i]     = __nv_bfloat162(__float2bfloat16(v.x - __bfloat162float(h0)),
                                   __float2bfloat16(v.y - __bfloat162float(h1)));
    lo[2 * i + 1] = __nv_bfloat162(__float2bfloat16(v.z - __bfloat162float(h2)),
                                   __float2bfloat16(v.w - __bfloat162float(h3)));
}

__global__ void k_half(const float4* __restrict__ in, __half2* __restrict__ out, int n4) {
    int i = blockIdx.x * 256 + threadIdx.x;
    if (i >= n4) return;
    float4 v = in[i];
    out[2 * i]     = __half2(__float2half_rn(v.x), __float2half_rn(v.y));
    out[2 * i + 1] = __half2(__float2half_rn(v.z), __float2half_rn(v.w));
}

// standalone W_out fp16 converter: wide grid, pure streaming
__global__ void __launch_bounds__(256) k_wout(const float4* __restrict__ wout,
                                              __half2* __restrict__ wo16) {
    int i = blockIdx.x * 256 + threadIdx.x;
    if (i >= 8192000) return;
    float4 v = wout[i];
    wo16[2 * i]     = __half2(__float2half_rn(v.x), __float2half_rn(v.y));
    wo16[2 * i + 1] = __half2(__float2half_rn(v.z), __float2half_rn(v.w));
}

// ===================== consolidated init =====================
__global__ void k_init(const int* __restrict__ y, const float* __restrict__ tab,
                       const float4* __restrict__ Wih,
                       const float* __restrict__ bih, const float* __restrict__ bhh) {
    const int bk = blockIdx.x, tid = threadIdx.x;
    if (bk < 512) {
        int i = bk * 256 + tid;
        int bs = i >> 6, e = i & 63;
        float4 v = ((const float4*)(tab + (long long)y[bs] * 256))[e];
        __nv_bfloat16 h0 = __float2bfloat16(v.x), h1 = __float2bfloat16(v.y);
        __nv_bfloat16 h2 = __float2bfloat16(v.z), h3 = __float2bfloat16(v.w);
        ((__nv_bfloat162*)s_emb_h)[2 * i]     = __nv_bfloat162(h0, h1);
        ((__nv_bfloat162*)s_emb_h)[2 * i + 1] = __nv_bfloat162(h2, h3);
        ((__nv_bfloat162*)s_emb_l)[2 * i]     = __nv_bfloat162(__float2bfloat16(v.x - __bfloat162float(h0)),
                                                               __float2bfloat16(v.y - __bfloat162float(h1)));
        ((__nv_bfloat162*)s_emb_l)[2 * i + 1] = __nv_bfloat162(__float2bfloat16(v.z - __bfloat162float(h2)),
                                                               __float2bfloat16(v.w - __bfloat162float(h3)));
    } else if (bk < 1024) {
        int i = (bk - 512) * 256 + tid;
        float4 v = Wih[i];
        __nv_bfloat16 h0 = __float2bfloat16(v.x), h1 = __float2bfloat16(v.y);
        __nv_bfloat16 h2 = __float2bfloat16(v.z), h3 = __float2bfloat16(v.w);
        ((__nv_bfloat162*)s_wih_h)[2 * i]     = __nv_bfloat162(h0, h1);
        ((__nv_bfloat162*)s_wih_h)[2 * i + 1] = __nv_bfloat162(h2, h3);
        ((__nv_bfloat162*)s_wih_l)[2 * i]     = __nv_bfloat162(__float2bfloat16(v.x - __bfloat162float(h0)),
                                                               __float2bfloat16(v.y - __bfloat162float(h1)));
        ((__nv_bfloat162*)s_wih_l)[2 * i + 1] = __nv_bfloat162(__float2bfloat16(v.z - __bfloat162float(h2)),
                                                               __float2bfloat16(v.w - __bfloat162float(h3)));
    } else {
        int i = (bk - 1024) * 256 + tid;
        if (i < 2048) g_bcomb[i] = bih[i] + bhh[i];
        if (i < 8192) g_hbuf[i] = 0.f;
        if (i == 0) g_bar = 0;
    }
}

__global__ void k_transpose(const float* __restrict__ in, float* __restrict__ out, int R, int C) {
    __shared__ float t[32][33];
    in += (long long)blockIdx.z * R * C;
    out += (long long)blockIdx.z * R * C;
    int c0 = blockIdx.x * 32, r0 = blockIdx.y * 32;
    int x = threadIdx.x, y = threadIdx.y;
#pragma unroll
    for (int i = 0; i < 32; i += 8)
        if (r0 + y + i < R && c0 + x < C) t[y + i][x] = in[(r0 + y + i) * C + c0 + x];
    __syncthreads();
#pragma unroll
    for (int i = 0; i < 32; i += 8)
        if (c0 + y + i < C && r0 + x < R) out[(c0 + y + i) * R + r0 + x] = t[x][y + i];
}

__global__ void k_softmax(const uint32_t* __restrict__ mask) {
    int w = (blockIdx.x * blockDim.x + threadIdx.x) >> 5;
    int lane = threadIdx.x & 31;
    if (w >= 2048) return;
    int b = w >> 7;
    const float* row = g_scores + w * 128;
    const uint32_t* m = mask + b * 128;
    float v[4];
    float mx = -1e30f;
#pragma unroll
    for (int i = 0; i < 4; i++) {
        int l = lane + 32 * i;
        v[i] = (m[l] != 0u) ? row[l] : -1e9f;
        mx = fmaxf(mx, v[i]);
    }
#pragma unroll
    for (int o = 16; o > 0; o >>= 1) mx = fmaxf(mx, __shfl_xor_sync(0xffffffffu, mx, o));
    float s = 0.f;
#pragma unroll
    for (int i = 0; i < 4; i++) { v[i] = expf(v[i] - mx); s += v[i]; }
#pragma unroll
    for (int o = 16; o > 0; o >>= 1) s += __shfl_xor_sync(0xffffffffu, s, o);
    float inv = 1.f / s;
#pragma unroll
    for (int i = 0; i < 4; i++) {
        float p = v[i] * inv;
        __nv_bfloat16 h = __float2bfloat16(p);
        int idx = w * 128 + lane + 32 * i;
        s_sc_h[idx] = h;
        s_sc_l[idx] = __float2bfloat16(p - __bfloat162float(h));
    }
}

// ===================== persistent LSTM (W in smem, 128 blocks, no co-tenants) ========
__device__ __forceinline__ void gridbar(unsigned target) {
    __syncthreads();
    if (threadIdx.x == 0) {
        __threadfence();
        atomicAdd(&g_bar, 1);
        while (*(volatile unsigned*)&g_bar < target) __nanosleep(32);
        __threadfence();
    }
    __syncthreads();
}

#define LSTM_SMEM ((8192 + 8192 + 4096 + 256) * 4)   // 82944 B

__global__ void __launch_bounds__(256) lstm_kernel(const float* __restrict__ xw) {
    const int tid = threadIdx.x, bk = blockIdx.x;

    extern __shared__ float smf[];
    float* w_sm = smf;
    float* h_sm = smf + 8192;
    float* red = smf + 16384;
    float* sgate = smf + 20480;

    const int u0 = bk * 4;

    for (int i = tid; i < 2048; i += 256) {
        int k = i >> 2, g = i & 3;
        ((float4*)w_sm)[k * 4 + g] = *(const float4*)(g_whhT + k * 2048 + g * 512 + u0);
    }

    const int ks = tid >> 4;
    const int bg = (tid >> 2) & 3;
    const int jg = tid & 3;
    const int b0 = bg * 4;
    const int rj = tid >> 4, rb = tid & 15;
    const int puu = tid >> 4, pbb = tid & 15;
    float creg = 0.f;

    const int gx = rj >> 2, uux = rj & 3;
    const float* xwp = xw + (long long)(rb * 128) * 2048 + gx * 512 + u0 + uux;
    float xw_cur = xwp[0];
    __syncthreads();

    for (int t = 0; t < 128; t++) {
#pragma unroll
        for (int i = tid; i < 2048; i += 256)
            ((float4*)h_sm)[i] = ((const float4*)g_hbuf)[i];
        __syncthreads();

        float a[4][4];
#pragma unroll
        for (int jj = 0; jj < 4; jj++)
#pragma unroll
            for (int bb = 0; bb < 4; bb++) a[jj][bb] = 0.f;

        const float* wp = w_sm + (ks * 32) * 16 + jg * 4;
        const float* hp = h_sm + (ks * 32) * 16 + b0;
#pragma unroll 8
        for (int k = 0; k < 32; k++) {
            float4 wv = *(const float4*)wp;
            float4 hv = *(const float4*)hp;
            wp += 16; hp += 16;
            float wa[4] = {wv.x, wv.y, wv.z, wv.w};
            float ha[4] = {hv.x, hv.y, hv.z, hv.w};
#pragma unroll
            for (int jj = 0; jj < 4; jj++)
#pragma unroll
                for (int bb = 0; bb < 4; bb++) a[jj][bb] = fmaf(wa[jj], ha[bb], a[jj][bb]);
        }
#pragma unroll
        for (int jj = 0; jj < 4; jj++)
#pragma unroll
            for (int bb = 0; bb < 4; bb++)
                red[ks * 256 + (jg * 4 + jj) * 16 + (bg * 4 + bb)] = a[jj][bb];
        __syncthreads();

        float s = 0.f;
#pragma unroll
        for (int q = 0; q < 16; q++) s += red[q * 256 + rj * 16 + rb];
        s += xw_cur;
        sgate[rj * 16 + rb] = s;
        __syncthreads();

        if (tid < 64) {
            float gi = sgate[(0 * 4 + puu) * 16 + pbb];
            float gf = sgate[(1 * 4 + puu) * 16 + pbb];
            float gg = sgate[(2 * 4 + puu) * 16 + pbb];
            float go = sgate[(3 * 4 + puu) * 16 + pbb];
            creg = sigm(gf) * creg + sigm(gi) * tanhf(gg);
            float h = sigm(go) * tanhf(creg);
            g_hbuf[(u0 + puu) * 16 + pbb] = h;
            g_cat[(pbb * 128 + t) * 1024 + u0 + puu] = h;
        }
        if (t + 1 < 128) xw_cur = xwp[(t + 1) * 2048];
        gridbar(128u * (t + 1));
    }
}

// ===================== host launcher =====================
extern "C" void kernel_launch(void* const* d_in, const int* in_sizes, int n_in,
                              void* d_out, int out_size) {
    const int* y = (const int*)d_in[0];
    const float* tab = (const float*)d_in[1];
    const float* Wih = (const float*)d_in[2];
    const float* Whh = (const float*)d_in[3];
    const float* bih = (const float*)d_in[4];
    const float* bhh = (const float*)d_in[5];
    const float* enc = (const float*)d_in[6];
    const uint32_t* mask = (const uint32_t*)d_in[7];
    const float* Wout = (const float*)d_in[8];
    const float* bout = (const float*)d_in[9];
    float* out = (float*)d_out;

    float *p_xw, *p_cat, *p_scores, *p_encT, *p_whhT, *p_bcomb;
    cudaGetSymbolAddress((void**)&p_xw, g_xw);
    cudaGetSymbolAddress((void**)&p_cat, g_cat);
    cudaGetSymbolAddress((void**)&p_scores, g_scores);
    cudaGetSymbolAddress((void**)&p_encT, g_encT);
    cudaGetSymbolAddress((void**)&p_whhT, g_whhT);
    cudaGetSymbolAddress((void**)&p_bcomb, g_bcomb);

    __nv_bfloat16 *e_h, *e_l, *wi_h, *wi_l, *c_h, *c_l;
    __nv_bfloat16 *en_h, *en_l, *et_h, *et_l, *sc_h, *sc_l;
    cudaGetSymbolAddress((void**)&e_h, s_emb_h);   cudaGetSymbolAddress((void**)&e_l, s_emb_l);
    cudaGetSymbolAddress((void**)&wi_h, s_wih_h);  cudaGetSymbolAddress((void**)&wi_l, s_wih_l);
    cudaGetSymbolAddress((void**)&c_h, s_cat_h);   cudaGetSymbolAddress((void**)&c_l, s_cat_l);
    cudaGetSymbolAddress((void**)&en_h, s_enc_h);  cudaGetSymbolAddress((void**)&en_l, s_enc_l);
    cudaGetSymbolAddress((void**)&et_h, s_encT_h); cudaGetSymbolAddress((void**)&et_l, s_encT_l);
    cudaGetSymbolAddress((void**)&sc_h, s_sc_h);   cudaGetSymbolAddress((void**)&sc_l, s_sc_l);

    __half *c16, *wo16;
    cudaGetSymbolAddress((void**)&c16, s_cat16);
    cudaGetSymbolAddress((void**)&wo16, s_wout16);

    cudaFuncSetAttribute(gemmb, cudaFuncAttributeMaxDynamicSharedMemorySize, 2 * STG_B);
    cudaFuncSetAttribute(gemmh, cudaFuncAttributeMaxDynamicSharedMemorySize, HSMEM);
    cudaFuncSetAttribute(lstm_kernel, cudaFuncAttributeMaxDynamicSharedMemorySize, LSTM_SMEM);

    // #1: consolidated init
    k_init<<<1056, 256>>>(y, tab, (const float4*)Wih, bih, bhh);

    // #2: xw = emb @ W_ih^T + (b_ih + b_hh)   [bf16 3-term]
    gemmb<<<dim3(16, 16, 1), 256, 2 * STG_B>>>(e_h, e_l, wi_h, wi_l, p_xw, p_bcomb,
                                               256, 256, 256, 2048, 0, 0, 0, 1.f);

    // #3: W_hh transpose
    k_transpose<<<dim3(16, 64, 1), dim3(32, 8)>>>(Whh, p_whhT, 2048, 512);

    // #4: LSTM, standalone (128 blocks, one per SM)   <-- ncu-profiled launch
    lstm_kernel<<<128, 256, LSTM_SMEM>>>(p_xw);

    // #5: W_out fp16 conversion, standalone wide grid
    k_wout<<<32000, 256>>>((const float4*)Wout, (__half2*)wo16);

    // enc prep
    k_transpose<<<dim3(16, 4, 16), dim3(32, 8)>>>(enc, p_encT, 128, 512);
    k_split<<<1024, 256>>>((const float4*)enc, (__nv_bfloat162*)en_h, (__nv_bfloat162*)en_l, 262144);
    k_split<<<1024, 256>>>((const float4*)p_encT, (__nv_bfloat162*)et_h, (__nv_bfloat162*)et_l, 262144);

    k_split<<<2048, 256>>>((const float4*)p_cat, (__nv_bfloat162*)c_h, (__nv_bfloat162*)c_l, 524288);

    // scores = dec @ enc^T / sqrt(H)        [bf16 3-term]
    gemmb<<<dim3(1, 1, 16), 256, 2 * STG_B>>>(c_h, c_l, en_h, en_l, p_scores, nullptr,
                                              512, 1024, 512, 128,
                                              131072LL, 65536LL, 16384LL,
                                              0.044194173824159216f);
    k_softmax<<<256, 256>>>(mask);

    // context = probs @ enc                 [bf16 3-term]
    gemmb<<<dim3(1, 4, 16), 256, 2 * STG_B>>>(sc_h, sc_l, et_h, et_l, p_cat + 512, nullptr,
                                              128, 128, 128, 1024,
                                              16384LL, 65536LL, 131072LL, 1.f);

    // cat -> fp16
    k_half<<<2048, 256>>>((const float4*)p_cat, (__half2*)c16, 524288);

    // logits = cat @ W_out^T + b_out        [fp16 1-term]
    gemmh<<<dim3(16, 250), 256, HSMEM>>>(c16, wo16, out, bout, 1024, 1024, 1024, 32000);
}

// round 14
// speedup vs baseline: 1.6346x; 1.0580x over previous
#include <cuda_runtime.h>
#include <cuda_bf16.h>
#include <cuda_fp16.h>
#include <cstdint>

// ===================== device scratch (static, no allocation) =====================
__device__ __align__(16) float g_xw[2048 * 2048];
__device__ __align__(16) float g_cat[2048 * 1024];
__device__ __align__(16) float g_scores[16 * 128 * 128];
__device__ __align__(16) float g_encT[16 * 512 * 128];
__device__ __align__(16) float g_whhT[512 * 2048];
__device__ __align__(16) float g_hbuf[2 * 512 * 8];   // per-group h: [gr][unit][8b]
__device__ __align__(16) float g_bcomb[2048];
__device__ unsigned g_bar2[2];

// bf16 3-term operands (small GEMMs)
__device__ __align__(16) __nv_bfloat16 s_emb_h[2048 * 256],  s_emb_l[2048 * 256];
__device__ __align__(16) __nv_bfloat16 s_wih_h[2048 * 256],  s_wih_l[2048 * 256];
__device__ __align__(16) __nv_bfloat16 s_cat_h[2048 * 1024], s_cat_l[2048 * 1024];
__device__ __align__(16) __nv_bfloat16 s_enc_h[16 * 128 * 512], s_enc_l[16 * 128 * 512];
__device__ __align__(16) __nv_bfloat16 s_encT_h[16 * 512 * 128], s_encT_l[16 * 512 * 128];
__device__ __align__(16) __nv_bfloat16 s_sc_h[16 * 128 * 128], s_sc_l[16 * 128 * 128];

// fp16 operands (output projection)
__device__ __align__(16) __half s_cat16[2048 * 1024];
__device__ __align__(16) __half s_wout16[32000 * 1024];

// ===================== helpers =====================
__device__ __forceinline__ float sigm(float x) { return 1.f / (1.f + expf(-x)); }

__device__ __forceinline__ void mma16b(float* d, const uint32_t* a, const uint32_t* b) {
    asm volatile(
        "mma.sync.aligned.m16n8k16.row.col.f32.bf16.bf16.f32 "
        "{%0,%1,%2,%3}, {%4,%5,%6,%7}, {%8,%9}, {%0,%1,%2,%3};"
        : "+f"(d[0]), "+f"(d[1]), "+f"(d[2]), "+f"(d[3])
        : "r"(a[0]), "r"(a[1]), "r"(a[2]), "r"(a[3]), "r"(b[0]), "r"(b[1]));
}

__device__ __forceinline__ void mma16h(float* d, const uint32_t* a, const uint32_t* b) {
    asm volatile(
        "mma.sync.aligned.m16n8k16.row.col.f32.f16.f16.f32 "
        "{%0,%1,%2,%3}, {%4,%5,%6,%7}, {%8,%9}, {%0,%1,%2,%3};"
        : "+f"(d[0]), "+f"(d[1]), "+f"(d[2]), "+f"(d[3])
        : "r"(a[0]), "r"(a[1]), "r"(a[2]), "r"(a[3]), "r"(b[0]), "r"(b[1]));
}

__device__ __forceinline__ void ldsm4(uint32_t& r0, uint32_t& r1, uint32_t& r2, uint32_t& r3,
                                      uint32_t addr) {
    asm volatile("ldmatrix.sync.aligned.m8n8.x4.shared.b16 {%0,%1,%2,%3}, [%4];"
                 : "=r"(r0), "=r"(r1), "=r"(r2), "=r"(r3) : "r"(addr));
}

__device__ __forceinline__ void cpasync16(uint32_t dst, const void* src) {
    asm volatile("cp.async.cg.shared.global [%0], [%1], 16;" :: "r"(dst), "l"(src));
}

// ===================== gemmh: fp16 out-GEMM (128x128 tile, K-chunk 64, 3-stage, 2 CTA/SM) ====
#define HPITCH 144
#define H_AB (128 * HPITCH)
#define HSTG (2 * H_AB)
#define HSMEM (3 * HSTG)

__global__ void __launch_bounds__(256, 2) gemmh(
    const __half* __restrict__ Ag, const __half* __restrict__ Bg,
    float* __restrict__ C, const float* __restrict__ bias,
    int K, int lda, int ldb, int ldc)
{
    extern __shared__ char smc[];
    const uint32_t sb = (uint32_t)__cvta_generic_to_shared(smc);

    const int m0 = blockIdx.x * 128, n0 = blockIdx.y * 128;
    const int tid = threadIdx.x, lane = tid & 31, warp = tid >> 5;
    const int wm = (warp & 1) * 64, wn = (warp >> 1) * 32;
    const int gid = lane >> 2, tig = lane & 3;
    const int rsel = lane & 15, csel = (lane >> 4) * 16;
    const int KT = K >> 6;

    float acc[4][4][4];
#pragma unroll
    for (int a = 0; a < 4; a++)
#pragma unroll
        for (int b = 0; b < 4; b++)
#pragma unroll
            for (int d = 0; d < 4; d++) acc[a][b][d] = 0.f;

#define HLOAD(KT_IDX, ST)                                                              \
    {                                                                                  \
        const int kof = (KT_IDX) * 64;                                                 \
        const uint32_t st = sb + (ST) * HSTG;                                          \
        _Pragma("unroll")                                                              \
        for (int i = 0; i < 4; i++) {                                                  \
            const int c = tid + 256 * i;                                               \
            const int row = c >> 3, off = c & 7;                                       \
            const uint32_t ad = st + row * HPITCH + off * 16;                          \
            cpasync16(ad,        Ag + (long long)(m0 + row) * lda + kof + off * 8);    \
            cpasync16(ad + H_AB, Bg + (long long)(n0 + row) * ldb + kof + off * 8);    \
        }                                                                              \
        asm volatile("cp.async.commit_group;");                                        \
    }

    HLOAD(0, 0);
    HLOAD(1, 1);

    for (int kt = 0; kt < KT; kt++) {
        if (kt + 2 < KT) asm volatile("cp.async.wait_group 1;");
        else             asm volatile("cp.async.wait_group 0;");
        __syncthreads();
        if (kt + 2 < KT) HLOAD(kt + 2, (kt + 2) % 3);

        const uint32_t base = sb + (kt % 3) * HSTG;
#pragma unroll
        for (int k16 = 0; k16 < 4; k16++) {
            const uint32_t kof = k16 * 32 + csel;
            uint32_t bh[4][2];
#pragma unroll
            for (int np = 0; np < 2; np++) {
                const uint32_t rb = base + H_AB + (wn + np * 16 + rsel) * HPITCH + kof;
                uint32_t t0, t1, t2, t3;
                ldsm4(t0, t1, t2, t3, rb);
                bh[2 * np][0] = t0; bh[2 * np][1] = t2;
                bh[2 * np + 1][0] = t1; bh[2 * np + 1][1] = t3;
            }
            uint32_t ah[4][4];
#pragma unroll
            for (int mf = 0; mf < 4; mf++) {
                const uint32_t ra = base + (wm + mf * 16 + rsel) * HPITCH + kof;
                ldsm4(ah[mf][0], ah[mf][1], ah[mf][2], ah[mf][3], ra);
            }
#pragma unroll
            for (int mf = 0; mf < 4; mf++)
#pragma unroll
                for (int nf = 0; nf < 4; nf++)
                    mma16h(acc[mf][nf], ah[mf], bh[nf]);
        }
    }

#pragma unroll
    for (int mf = 0; mf < 4; mf++) {
        const int r = m0 + wm + mf * 16 + gid;
#pragma unroll
        for (int nf = 0; nf < 4; nf++) {
            const int c = n0 + wn + nf * 8 + 2 * tig;
            float b0 = bias[c], b1 = bias[c + 1];
            float2 v0 = {acc[mf][nf][0] + b0, acc[mf][nf][1] + b1};
            float2 v1 = {acc[mf][nf][2] + b0, acc[mf][nf][3] + b1};
            *(float2*)&C[(long long)r * ldc + c] = v0;
            *(float2*)&C[(long long)(r + 8) * ldc + c] = v1;
        }
    }
}

// ===================== gemmb: bf16 3-term (small/batched GEMMs) =====
#define PITCH 80
#define MAT_B (128 * PITCH)
#define STG_B (4 * MAT_B)

__global__ void __launch_bounds__(256, 2) gemmb(
    const __nv_bfloat16* __restrict__ Ahg, const __nv_bfloat16* __restrict__ Alg,
    const __nv_bfloat16* __restrict__ Bhg, const __nv_bfloat16* __restrict__ Blg,
    float* __restrict__ C, const float* __restrict__ bias,
    int K, int lda, int ldb, int ldc,
    long long sA, long long sB, long long sC, float alpha)
{
    extern __shared__ char smc[];
    const uint32_t sb = (uint32_t)__cvta_generic_to_shared(smc);

    Ahg += sA * blockIdx.z; Alg += sA * blockIdx.z;
    Bhg += sB * blockIdx.z; Blg += sB * blockIdx.z;
    C += sC * blockIdx.z;

    const int m0 = blockIdx.x * 128, n0 = blockIdx.y * 128;
    const int tid = threadIdx.x, lane = tid & 31, warp = tid >> 5;
    const int wm = (warp & 1) * 64, wn = (warp >> 1) * 32;
    const int gid = lane >> 2, tig = lane & 3;
    const int rsel = lane & 15, csel = (lane >> 4) * 16;
    const int KT = K >> 5;
    const int lrow = tid >> 2, loff = tid & 3;

    float acc[4][4][4];
#pragma unroll
    for (int a = 0; a < 4; a++)
#pragma unroll
        for (int b = 0; b < 4; b++)
#pragma unroll
            for (int d = 0; d < 4; d++) acc[a][b][d] = 0.f;

#define LOAD_STAGE(KT_IDX, ST)                                                          \
    {                                                                                   \
        const int kofs = (KT_IDX) * 32 + loff * 8;                                      \
        const uint32_t db = sb + (ST) * STG_B + lrow * PITCH + loff * 16;               \
        cpasync16(db,                  Ahg + (long long)(m0 + lrow) * lda + kofs);      \
        cpasync16(db + 64 * PITCH,     Ahg + (long long)(m0 + lrow + 64) * lda + kofs); \
        cpasync16(db + MAT_B,          Alg + (long long)(m0 + lrow) * lda + kofs);      \
        cpasync16(db + MAT_B + 64 * PITCH, Alg + (long long)(m0 + lrow + 64) * lda + kofs); \
        cpasync16(db + 2 * MAT_B,      Bhg + (long long)(n0 + lrow) * ldb + kofs);      \
        cpasync16(db + 2 * MAT_B + 64 * PITCH, Bhg + (long long)(n0 + lrow + 64) * ldb + kofs); \
        cpasync16(db + 3 * MAT_B,      Blg + (long long)(n0 + lrow) * ldb + kofs);      \
        cpasync16(db + 3 * MAT_B + 64 * PITCH, Blg + (long long)(n0 + lrow + 64) * ldb + kofs); \
        asm volatile("cp.async.commit_group;");                                         \
    }

    LOAD_STAGE(0, 0);

    for (int kt = 0; kt < KT; kt++) {
        if (kt + 1 < KT) {
            LOAD_STAGE(kt + 1, (kt + 1) & 1);
            asm volatile("cp.async.wait_group 1;");
        } else {
            asm volatile("cp.async.wait_group 0;");
        }
        __syncthreads();

        const uint32_t base = sb + (kt & 1) * STG_B;
#pragma unroll
        for (int k16 = 0; k16 < 2; k16++) {
            const uint32_t kof = k16 * 32 + csel;
            uint32_t bh[4][2], bl[4][2];
#pragma unroll
            for (int np = 0; np < 2; np++) {
                const uint32_t rb = base + 2 * MAT_B + (wn + np * 16 + rsel) * PITCH + kof;
                uint32_t t0, t1, t2, t3;
                ldsm4(t0, t1, t2, t3, rb);
                bh[2 * np][0] = t0; bh[2 * np][1] = t2;
                bh[2 * np + 1][0] = t1; bh[2 * np + 1][1] = t3;
                ldsm4(t0, t1, t2, t3, rb + MAT_B);
                bl[2 * np][0] = t0; bl[2 * np][1] = t2;
                bl[2 * np + 1][0] = t1; bl[2 * np + 1][1] = t3;
            }
#pragma unroll
            for (int mg = 0; mg < 2; mg++) {
                uint32_t ah[2][4], al[2][4];
#pragma unroll
                for (int mi = 0; mi < 2; mi++) {
                    const uint32_t ra = base + (wm + (mg * 2 + mi) * 16 + rsel) * PITCH + kof;
                    ldsm4(ah[mi][0], ah[mi][1], ah[mi][2], ah[mi][3], ra);
                    ldsm4(al[mi][0], al[mi][1], al[mi][2], al[mi][3], ra + MAT_B);
                }
#pragma unroll
                for (int mi = 0; mi < 2; mi++)
#pragma unroll
                    for (int nf = 0; nf < 4; nf++)
                        mma16b(acc[mg * 2 + mi][nf], ah[mi], bh[nf]);
#pragma unroll
                for (int mi = 0; mi < 2; mi++)
#pragma unroll
                    for (int nf = 0; nf < 4; nf++)
                        mma16b(acc[mg * 2 + mi][nf], ah[mi], bl[nf]);
#pragma unroll
                for (int mi = 0; mi < 2; mi++)
#pragma unroll
                    for (int nf = 0; nf < 4; nf++)
                        mma16b(acc[mg * 2 + mi][nf], al[mi], bh[nf]);
            }
        }
        __syncthreads();
    }

#pragma unroll
    for (int mf = 0; mf < 4; mf++) {
        const int r = m0 + wm + mf * 16 + gid;
#pragma unroll
        for (int nf = 0; nf < 4; nf++) {
            const int c = n0 + wn + nf * 8 + 2 * tig;
            float b0 = bias ? bias[c] : 0.f;
            float b1 = bias ? bias[c + 1] : 0.f;
            float2 v0 = {alpha * acc[mf][nf][0] + b0, alpha * acc[mf][nf][1] + b1};
            float2 v1 = {alpha * acc[mf][nf][2] + b0, alpha * acc[mf][nf][3] + b1};
            *(float2*)&C[(long long)r * ldc + c] = v0;
            *(float2*)&C[(long long)(r + 8) * ldc + c] = v1;
        }
    }
}

// ===================== split / convert kernels =====================
__global__ void k_split(const float4* __restrict__ in, __nv_bfloat162* __restrict__ hi,
                        __nv_bfloat162* __restrict__ lo, int n4) {
    int i = blockIdx.x * 256 + threadIdx.x;
    if (i >= n4) return;
    float4 v = in[i];
    __nv_bfloat16 h0 = __float2bfloat16(v.x), h1 = __float2bfloat16(v.y);
    __nv_bfloat16 h2 = __float2bfloat16(v.z), h3 = __float2bfloat16(v.w);
    hi[2 * i]     = __nv_bfloat162(h0, h1);
    hi[2 * i + 1] = __nv_bfloat162(h2, h3);
    lo[2 * i]     = __nv_bfloat162(__float2bfloat16(v.x - __bfloat162float(h0)),
                                   __float2bfloat16(v.y - __bfloat162float(h1)));
    lo[2 * i + 1] = __nv_bfloat162(__float2bfloat16(v.z - __bfloat162float(h2)),
                                   __float2bfloat16(v.w - __bfloat162float(h3)));
}

__global__ void k_half(const float4* __restrict__ in, __half2* __restrict__ out, int n4) {
    int i = blockIdx.x * 256 + threadIdx.x;
    if (i >= n4) return;
    float4 v = in[i];
    out[2 * i]     = __half2(__float2half_rn(v.x), __float2half_rn(v.y));
    out[2 * i + 1] = __half2(__float2half_rn(v.z), __float2half_rn(v.w));
}

__global__ void __launch_bounds__(256) k_wout(const float4* __restrict__ wout,
                                              __half2* __restrict__ wo16) {
    int i = blockIdx.x * 256 + threadIdx.x;
    if (i >= 8192000) return;
    float4 v = wout[i];
    wo16[2 * i]     = __half2(__float2half_rn(v.x), __float2half_rn(v.y));
    wo16[2 * i + 1] = __half2(__float2half_rn(v.z), __float2half_rn(v.w));
}

// ===================== consolidated init =====================
__global__ void k_init(const int* __restrict__ y, const float* __restrict__ tab,
                       const float4* __restrict__ Wih,
                       const float* __restrict__ bih, const float* __restrict__ bhh) {
    const int bk = blockIdx.x, tid = threadIdx.x;
    if (bk < 512) {
        int i = bk * 256 + tid;
        int bs = i >> 6, e = i & 63;
        float4 v = ((const float4*)(tab + (long long)y[bs] * 256))[e];
        __nv_bfloat16 h0 = __float2bfloat16(v.x), h1 = __float2bfloat16(v.y);
        __nv_bfloat16 h2 = __float2bfloat16(v.z), h3 = __float2bfloat16(v.w);
        ((__nv_bfloat162*)s_emb_h)[2 * i]     = __nv_bfloat162(h0, h1);
        ((__nv_bfloat162*)s_emb_h)[2 * i + 1] = __nv_bfloat162(h2, h3);
        ((__nv_bfloat162*)s_emb_l)[2 * i]     = __nv_bfloat162(__float2bfloat16(v.x - __bfloat162float(h0)),
                                                               __float2bfloat16(v.y - __bfloat162float(h1)));
        ((__nv_bfloat162*)s_emb_l)[2 * i + 1] = __nv_bfloat162(__float2bfloat16(v.z - __bfloat162float(h2)),
                                                               __float2bfloat16(v.w - __bfloat162float(h3)));
    } else if (bk < 1024) {
        int i = (bk - 512) * 256 + tid;
        float4 v = Wih[i];
        __nv_bfloat16 h0 = __float2bfloat16(v.x), h1 = __float2bfloat16(v.y);
        __nv_bfloat16 h2 = __float2bfloat16(v.z), h3 = __float2bfloat16(v.w);
        ((__nv_bfloat162*)s_wih_h)[2 * i]     = __nv_bfloat162(h0, h1);
        ((__nv_bfloat162*)s_wih_h)[2 * i + 1] = __nv_bfloat162(h2, h3);
        ((__nv_bfloat162*)s_wih_l)[2 * i]     = __nv_bfloat162(__float2bfloat16(v.x - __bfloat162float(h0)),
                                                               __float2bfloat16(v.y - __bfloat162float(h1)));
        ((__nv_bfloat162*)s_wih_l)[2 * i + 1] = __nv_bfloat162(__float2bfloat16(v.z - __bfloat162float(h2)),
                                                               __float2bfloat16(v.w - __bfloat162float(h3)));
    } else {
        int i = (bk - 1024) * 256 + tid;
        if (i < 2048) g_bcomb[i] = bih[i] + bhh[i];
        if (i < 8192) g_hbuf[i] = 0.f;
        if (i < 2) g_bar2[i] = 0;
    }
}

__global__ void k_transpose(const float* __restrict__ in, float* __restrict__ out, int R, int C) {
    __shared__ float t[32][33];
    in += (long long)blockIdx.z * R * C;
    out += (long long)blockIdx.z * R * C;
    int c0 = blockIdx.x * 32, r0 = blockIdx.y * 32;
    int x = threadIdx.x, y = threadIdx.y;
#pragma unroll
    for (int i = 0; i < 32; i += 8)
        if (r0 + y + i < R && c0 + x < C) t[y + i][x] = in[(r0 + y + i) * C + c0 + x];
    __syncthreads();
#pragma unroll
    for (int i = 0; i < 32; i += 8)
        if (c0 + y + i < C && r0 + x < R) out[(c0 + y + i) * R + r0 + x] = t[x][y + i];
}

__global__ void k_softmax(const uint32_t* __restrict__ mask) {
    int w = (blockIdx.x * blockDim.x + threadIdx.x) >> 5;
    int lane = threadIdx.x & 31;
    if (w >= 2048) return;
    int b = w >> 7;
    const float* row = g_scores + w * 128;
    const uint32_t* m = mask + b * 128;
    float v[4];
    float mx = -1e30f;
#pragma unroll
    for (int i = 0; i < 4; i++) {
        int l = lane + 32 * i;
        v[i] = (m[l] != 0u) ? row[l] : -1e9f;
        mx = fmaxf(mx, v[i]);
    }
#pragma unroll
    for (int o = 16; o > 0; o >>= 1) mx = fmaxf(mx, __shfl_xor_sync(0xffffffffu, mx, o));
    float s = 0.f;
#pragma unroll
    for (int i = 0; i < 4; i++) { v[i] = expf(v[i] - mx); s += v[i]; }
#pragma unroll
    for (int o = 16; o > 0; o >>= 1) s += __shfl_xor_sync(0xffffffffu, s, o);
    float inv = 1.f / s;
#pragma unroll
    for (int i = 0; i < 4; i++) {
        float p = v[i] * inv;
        __nv_bfloat16 h = __float2bfloat16(p);
        int idx = w * 128 + lane + 32 * i;
        s_sc_h[idx] = h;
        s_sc_l[idx] = __float2bfloat16(p - __bfloat162float(h));
    }
}

// ===================== LSTM: 2 groups x 128 blocks, 128 thr, 2 blocks/SM overlap ====
// group gr handles batches gr*8..gr*8+7; block bi owns units u0=bi*4 (16 gate rows).
// smem: w 520*16=8320f (chunk-padded), h 260*16=4160f, red 2048f, sgate 128f.
#define LSTM_SMEM ((8320 + 4160 + 2048 + 128) * 4)   // 58624 B

__global__ void __launch_bounds__(128, 2) lstm_kernel(const float* __restrict__ xw) {
    const int tid = threadIdx.x, bk = blockIdx.x;
    const int gr = bk >> 7, bi = bk & 127;
    const int u0 = bi * 4;

    extern __shared__ float smf[];
    float* w_sm = smf;            // idx: k*16 + (k>>5)*8 + jl   (jl = g*4+uu)
    float* h_sm = smf + 8320;     // idx: k*8  + (k>>5)*4 + b
    float* red = smf + 12480;     // [16ks][16jl][8b]
    float* sgate = smf + 14528;   // [16jl][8b]

    float* ghb = g_hbuf + gr * 4096;           // [512][8]
    unsigned* barp = &g_bar2[gr];

    // load W slice once: i over 2048 float4 (k 0..511, g 0..3)
    for (int i = tid; i < 2048; i += 128) {
        int k = i >> 2, g = i & 3;
        ((float4*)w_sm)[k * 4 + (k >> 5) * 2 + g] =
            *(const float4*)(g_whhT + k * 2048 + g * 512 + u0);
    }

    const int ks = tid >> 3;            // 0..15
    const int jg = tid & 7;             // 0..7 -> jl0 = jg*2
    const int jl0 = jg * 2;
    const int rjl = tid >> 3, rbb = tid & 7;
    const int gx = rjl >> 2, uux = rjl & 3;
    const int puu = tid >> 3, pb = tid & 7;   // update: threads 0..31
    float creg = 0.f;

    const float* xwp = xw + (long long)((gr * 8 + rbb) * 128) * 2048 + gx * 512 + u0 + uux;
    float xw_cur = xwp[0];
    __syncthreads();

    for (int t = 0; t < 128; t++) {
        // h broadcast: 1024 float4 (with chunk padding)
#pragma unroll
        for (int i = tid; i < 1024; i += 128) {
            int k = i >> 1, half = i & 1;
            ((float4*)h_sm)[k * 2 + (k >> 5) + half] = ((const float4*)ghb)[i];
        }
        __syncthreads();

        float a[2][8];
#pragma unroll
        for (int jj = 0; jj < 2; jj++)
#pragma unroll
            for (int bb = 0; bb < 8; bb++) a[jj][bb] = 0.f;

        const float* wp = w_sm + ks * 520 + jl0;
        const float* hp = h_sm + ks * 260;
#pragma unroll 8
        for (int k = 0; k < 32; k++) {
            float2 wv = *(const float2*)(wp + k * 16);
            float4 h0 = *(const float4*)(hp + k * 8);
            float4 h1 = *(const float4*)(hp + k * 8 + 4);
            float hb[8] = {h0.x, h0.y, h0.z, h0.w, h1.x, h1.y, h1.z, h1.w};
#pragma unroll
            for (int bb = 0; bb < 8; bb++) {
                a[0][bb] = fmaf(wv.x, hb[bb], a[0][bb]);
                a[1][bb] = fmaf(wv.y, hb[bb], a[1][bb]);
            }
        }
#pragma unroll
        for (int jj = 0; jj < 2; jj++)
#pragma unroll
            for (int bb = 0; bb < 8; bb++)
                red[ks * 128 + (jl0 + jj) * 8 + bb] = a[jj][bb];
        __syncthreads();

        float s = 0.f;
#pragma unroll
        for (int q = 0; q < 16; q++) s += red[q * 128 + rjl * 8 + rbb];
        s += xw_cur;
        sgate[rjl * 8 + rbb] = s;
        __syncthreads();

        if (tid < 32) {
            float gi = sgate[(0 * 4 + puu) * 8 + pb];
            float gf = sgate[(1 * 4 + puu) * 8 + pb];
            float gg = sgate[(2 * 4 + puu) * 8 + pb];
            float go = sgate[(3 * 4 + puu) * 8 + pb];
            creg = sigm(gf) * creg + sigm(gi) * tanhf(gg);
            float h = sigm(go) * tanhf(creg);
            ghb[(u0 + puu) * 8 + pb] = h;
            g_cat[((gr * 8 + pb) * 128 + t) * 1024 + u0 + puu] = h;
        }
        if (t + 1 < 128) xw_cur = xwp[(t + 1) * 2048];

        // per-group grid barrier (monotonic)
        __syncthreads();
        if (tid == 0) {
            __threadfence();
            atomicAdd(barp, 1);
            unsigned target = 128u * (t + 1);
            while (*(volatile unsigned*)barp < target) __nanosleep(32);
            __threadfence();
        }
        __syncthreads();
    }
}

// ===================== host launcher =====================
extern "C" void kernel_launch(void* const* d_in, const int* in_sizes, int n_in,
                              void* d_out, int out_size) {
    const int* y = (const int*)d_in[0];
    const float* tab = (const float*)d_in[1];
    const float* Wih = (const float*)d_in[2];
    const float* Whh = (const float*)d_in[3];
    const float* bih = (const float*)d_in[4];
    const float* bhh = (const float*)d_in[5];
    const float* enc = (const float*)d_in[6];
    const uint32_t* mask = (const uint32_t*)d_in[7];
    const float* Wout = (const float*)d_in[8];
    const float* bout = (const float*)d_in[9];
    float* out = (float*)d_out;

    float *p_xw, *p_cat, *p_scores, *p_encT, *p_whhT, *p_bcomb;
    cudaGetSymbolAddress((void**)&p_xw, g_xw);
    cudaGetSymbolAddress((void**)&p_cat, g_cat);
    cudaGetSymbolAddress((void**)&p_scores, g_scores);
    cudaGetSymbolAddress((void**)&p_encT, g_encT);
    cudaGetSymbolAddress((void**)&p_whhT, g_whhT);
    cudaGetSymbolAddress((void**)&p_bcomb, g_bcomb);

    __nv_bfloat16 *e_h, *e_l, *wi_h, *wi_l, *c_h, *c_l;
    __nv_bfloat16 *en_h, *en_l, *et_h, *et_l, *sc_h, *sc_l;
    cudaGetSymbolAddress((void**)&e_h, s_emb_h);   cudaGetSymbolAddress((void**)&e_l, s_emb_l);
    cudaGetSymbolAddress((void**)&wi_h, s_wih_h);  cudaGetSymbolAddress((void**)&wi_l, s_wih_l);
    cudaGetSymbolAddress((void**)&c_h, s_cat_h);   cudaGetSymbolAddress((void**)&c_l, s_cat_l);
    cudaGetSymbolAddress((void**)&en_h, s_enc_h);  cudaGetSymbolAddress((void**)&en_l, s_enc_l);
    cudaGetSymbolAddress((void**)&et_h, s_encT_h); cudaGetSymbolAddress((void**)&et_l, s_encT_l);
    cudaGetSymbolAddress((void**)&sc_h, s_sc_h);   cudaGetSymbolAddress((void**)&sc_l, s_sc_l);

    __half *c16, *wo16;
    cudaGetSymbolAddress((void**)&c16, s_cat16);
    cudaGetSymbolAddress((void**)&wo16, s_wout16);

    cudaFuncSetAttribute(gemmb, cudaFuncAttributeMaxDynamicSharedMemorySize, 2 * STG_B);
    cudaFuncSetAttribute(gemmh, cudaFuncAttributeMaxDynamicSharedMemorySize, HSMEM);
    cudaFuncSetAttribute(lstm_kernel, cudaFuncAttributeMaxDynamicSharedMemorySize, LSTM_SMEM);

    // #1: consolidated init
    k_init<<<1056, 256>>>(y, tab, (const float4*)Wih, bih, bhh);

    // #2: xw = emb @ W_ih^T + (b_ih + b_hh)   [bf16 3-term]
    gemmb<<<dim3(16, 16, 1), 256, 2 * STG_B>>>(e_h, e_l, wi_h, wi_l, p_xw, p_bcomb,
                                               256, 256, 256, 2048, 0, 0, 0, 1.f);

    // #3: W_hh transpose
    k_transpose<<<dim3(16, 64, 1), dim3(32, 8)>>>(Whh, p_whhT, 2048, 512);

    // #4: LSTM, 2 groups x 128 blocks, 2 blocks/SM   <-- ncu-profiled launch
    lstm_kernel<<<256, 128, LSTM_SMEM>>>(p_xw);

    // #5: W_out fp16 conversion
    k_wout<<<32000, 256>>>((const float4*)Wout, (__half2*)wo16);

    // enc prep
    k_transpose<<<dim3(16, 4, 16), dim3(32, 8)>>>(enc, p_encT, 128, 512);
    k_split<<<1024, 256>>>((const float4*)enc, (__nv_bfloat162*)en_h, (__nv_bfloat162*)en_l, 262144);
    k_split<<<1024, 256>>>((const float4*)p_encT, (__nv_bfloat162*)et_h, (__nv_bfloat162*)et_l, 262144);

    k_split<<<2048, 256>>>((const float4*)p_cat, (__nv_bfloat162*)c_h, (__nv_bfloat162*)c_l, 524288);

    // scores = dec @ enc^T / sqrt(H)        [bf16 3-term]
    gemmb<<<dim3(1, 1, 16), 256, 2 * STG_B>>>(c_h, c_l, en_h, en_l, p_scores, nullptr,
                                              512, 1024, 512, 128,
                                              131072LL, 65536LL, 16384LL,
                                              0.044194173824159216f);
    k_softmax<<<256, 256>>>(mask);

    // context = probs @ enc                 [bf16 3-term]
    gemmb<<<dim3(1, 4, 16), 256, 2 * STG_B>>>(sc_h, sc_l, et_h, et_l, p_cat + 512, nullptr,
                                              128, 128, 128, 1024,
                                              16384LL, 65536LL, 131072LL, 1.f);

    // cat -> fp16
    k_half<<<2048, 256>>>((const float4*)p_cat, (__half2*)c16, 524288);

    // logits = cat @ W_out^T + b_out        [fp16 1-term]
    gemmh<<<dim3(16, 250), 256, HSMEM>>>(c16, wo16, out, bout, 1024, 1024, 1024, 32000);
}

// round 15
// speedup vs baseline: 1.6421x; 1.0046x over previous
#include <cuda_runtime.h>
#include <cuda_bf16.h>
#include <cuda_fp16.h>
#include <cstdint>

// ===================== device scratch (static, no allocation) =====================
__device__ __align__(16) float g_xw[2048 * 2048];
__device__ __align__(16) float g_cat[2048 * 1024];
__device__ __align__(16) float g_scores[16 * 128 * 128];
__device__ __align__(16) float g_encT[16 * 512 * 128];
__device__ __align__(16) float g_whhT[512 * 2048];
__device__ __align__(16) float g_hbuf[2 * 512 * 8];   // per-group h: [gr][unit][8b]
__device__ __align__(16) float g_bcomb[2048];
__device__ unsigned g_bar2[2];

// bf16 3-term operands (small GEMMs)
__device__ __align__(16) __nv_bfloat16 s_emb_h[2048 * 256],  s_emb_l[2048 * 256];
__device__ __align__(16) __nv_bfloat16 s_wih_h[2048 * 256],  s_wih_l[2048 * 256];
__device__ __align__(16) __nv_bfloat16 s_cat_h[2048 * 1024], s_cat_l[2048 * 1024];
__device__ __align__(16) __nv_bfloat16 s_enc_h[16 * 128 * 512], s_enc_l[16 * 128 * 512];
__device__ __align__(16) __nv_bfloat16 s_encT_h[16 * 512 * 128], s_encT_l[16 * 512 * 128];
__device__ __align__(16) __nv_bfloat16 s_sc_h[16 * 128 * 128], s_sc_l[16 * 128 * 128];

// fp16 operands (output projection)
__device__ __align__(16) __half s_cat16[2048 * 1024];
__device__ __align__(16) __half s_wout16[32000 * 1024];

// ===================== helpers =====================
__device__ __forceinline__ float fsigm(float x) {
    return __frcp_rn(1.f + __expf(-x));
}
__device__ __forceinline__ float ftanh(float x) {
    x = fminf(fmaxf(x, -15.f), 15.f);
    float e = __expf(2.f * x);
    return (e - 1.f) * __frcp_rn(e + 1.f);
}

__device__ __forceinline__ void mma16b(float* d, const uint32_t* a, const uint32_t* b) {
    asm volatile(
        "mma.sync.aligned.m16n8k16.row.col.f32.bf16.bf16.f32 "
        "{%0,%1,%2,%3}, {%4,%5,%6,%7}, {%8,%9}, {%0,%1,%2,%3};"
        : "+f"(d[0]), "+f"(d[1]), "+f"(d[2]), "+f"(d[3])
        : "r"(a[0]), "r"(a[1]), "r"(a[2]), "r"(a[3]), "r"(b[0]), "r"(b[1]));
}

__device__ __forceinline__ void mma16h(float* d, const uint32_t* a, const uint32_t* b) {
    asm volatile(
        "mma.sync.aligned.m16n8k16.row.col.f32.f16.f16.f32 "
        "{%0,%1,%2,%3}, {%4,%5,%6,%7}, {%8,%9}, {%0,%1,%2,%3};"
        : "+f"(d[0]), "+f"(d[1]), "+f"(d[2]), "+f"(d[3])
        : "r"(a[0]), "r"(a[1]), "r"(a[2]), "r"(a[3]), "r"(b[0]), "r"(b[1]));
}

__device__ __forceinline__ void ldsm4(uint32_t& r0, uint32_t& r1, uint32_t& r2, uint32_t& r3,
                                      uint32_t addr) {
    asm volatile("ldmatrix.sync.aligned.m8n8.x4.shared.b16 {%0,%1,%2,%3}, [%4];"
                 : "=r"(r0), "=r"(r1), "=r"(r2), "=r"(r3) : "r"(addr));
}

__device__ __forceinline__ void cpasync16(uint32_t dst, const void* src) {
    asm volatile("cp.async.cg.shared.global [%0], [%1], 16;" :: "r"(dst), "l"(src));
}

// ===================== gemmh: fp16 out-GEMM (128x128 tile, K-chunk 64, 3-stage, 2 CTA/SM) ====
#define HPITCH 144
#define H_AB (128 * HPITCH)
#define HSTG (2 * H_AB)
#define HSMEM (3 * HSTG)

__global__ void __launch_bounds__(256, 2) gemmh(
    const __half* __restrict__ Ag, const __half* __restrict__ Bg,
    float* __restrict__ C, const float* __restrict__ bias,
    int K, int lda, int ldb, int ldc)
{
    extern __shared__ char smc[];
    const uint32_t sb = (uint32_t)__cvta_generic_to_shared(smc);

    const int m0 = blockIdx.x * 128, n0 = blockIdx.y * 128;
    const int tid = threadIdx.x, lane = tid & 31, warp = tid >> 5;
    const int wm = (warp & 1) * 64, wn = (warp >> 1) * 32;
    const int gid = lane >> 2, tig = lane & 3;
    const int rsel = lane & 15, csel = (lane >> 4) * 16;
    const int KT = K >> 6;

    float acc[4][4][4];
#pragma unroll
    for (int a = 0; a < 4; a++)
#pragma unroll
        for (int b = 0; b < 4; b++)
#pragma unroll
            for (int d = 0; d < 4; d++) acc[a][b][d] = 0.f;

#define HLOAD(KT_IDX, ST)                                                              \
    {                                                                                  \
        const int kof = (KT_IDX) * 64;                                                 \
        const uint32_t st = sb + (ST) * HSTG;                                          \
        _Pragma("unroll")                                                              \
        for (int i = 0; i < 4; i++) {                                                  \
            const int c = tid + 256 * i;                                               \
            const int row = c >> 3, off = c & 7;                                       \
            const uint32_t ad = st + row * HPITCH + off * 16;                          \
            cpasync16(ad,        Ag + (long long)(m0 + row) * lda + kof + off * 8);    \
            cpasync16(ad + H_AB, Bg + (long long)(n0 + row) * ldb + kof + off * 8);    \
        }                                                                              \
        asm volatile("cp.async.commit_group;");                                        \
    }

    HLOAD(0, 0);
    HLOAD(1, 1);

    for (int kt = 0; kt < KT; kt++) {
        if (kt + 2 < KT) asm volatile("cp.async.wait_group 1;");
        else             asm volatile("cp.async.wait_group 0;");
        __syncthreads();
        if (kt + 2 < KT) HLOAD(kt + 2, (kt + 2) % 3);

        const uint32_t base = sb + (kt % 3) * HSTG;
#pragma unroll
        for (int k16 = 0; k16 < 4; k16++) {
            const uint32_t kof = k16 * 32 + csel;
            uint32_t bh[4][2];
#pragma unroll
            for (int np = 0; np < 2; np++) {
                const uint32_t rb = base + H_AB + (wn + np * 16 + rsel) * HPITCH + kof;
                uint32_t t0, t1, t2, t3;
                ldsm4(t0, t1, t2, t3, rb);
                bh[2 * np][0] = t0; bh[2 * np][1] = t2;
                bh[2 * np + 1][0] = t1; bh[2 * np + 1][1] = t3;
            }
            uint32_t ah[4][4];
#pragma unroll
            for (int mf = 0; mf < 4; mf++) {
                const uint32_t ra = base + (wm + mf * 16 + rsel) * HPITCH + kof;
                ldsm4(ah[mf][0], ah[mf][1], ah[mf][2], ah[mf][3], ra);
            }
#pragma unroll
            for (int mf = 0; mf < 4; mf++)
#pragma unroll
                for (int nf = 0; nf < 4; nf++)
                    mma16h(acc[mf][nf], ah[mf], bh[nf]);
        }
    }

#pragma unroll
    for (int mf = 0; mf < 4; mf++) {
        const int r = m0 + wm + mf * 16 + gid;
#pragma unroll
        for (int nf = 0; nf < 4; nf++) {
            const int c = n0 + wn + nf * 8 + 2 * tig;
            float b0 = bias[c], b1 = bias[c + 1];
            float2 v0 = {acc[mf][nf][0] + b0, acc[mf][nf][1] + b1};
            float2 v1 = {acc[mf][nf][2] + b0, acc[mf][nf][3] + b1};
            *(float2*)&C[(long long)r * ldc + c] = v0;
            *(float2*)&C[(long long)(r + 8) * ldc + c] = v1;
        }
    }
}

// ===================== gemmb: bf16 3-term (small/batched GEMMs) =====
#define PITCH 80
#define MAT_B (128 * PITCH)
#define STG_B (4 * MAT_B)

__global__ void __launch_bounds__(256, 2) gemmb(
    const __nv_bfloat16* __restrict__ Ahg, const __nv_bfloat16* __restrict__ Alg,
    const __nv_bfloat16* __restrict__ Bhg, const __nv_bfloat16* __restrict__ Blg,
    float* __restrict__ C, const float* __restrict__ bias,
    int K, int lda, int ldb, int ldc,
    long long sA, long long sB, long long sC, float alpha)
{
    extern __shared__ char smc[];
    const uint32_t sb = (uint32_t)__cvta_generic_to_shared(smc);

    Ahg += sA * blockIdx.z; Alg += sA * blockIdx.z;
    Bhg += sB * blockIdx.z; Blg += sB * blockIdx.z;
    C += sC * blockIdx.z;

    const int m0 = blockIdx.x * 128, n0 = blockIdx.y * 128;
    const int tid = threadIdx.x, lane = tid & 31, warp = tid >> 5;
    const int wm = (warp & 1) * 64, wn = (warp >> 1) * 32;
    const int gid = lane >> 2, tig = lane & 3;
    const int rsel = lane & 15, csel = (lane >> 4) * 16;
    const int KT = K >> 5;
    const int lrow = tid >> 2, loff = tid & 3;

    float acc[4][4][4];
#pragma unroll
    for (int a = 0; a < 4; a++)
#pragma unroll
        for (int b = 0; b < 4; b++)
#pragma unroll
            for (int d = 0; d < 4; d++) acc[a][b][d] = 0.f;

#define LOAD_STAGE(KT_IDX, ST)                                                          \
    {                                                                                   \
        const int kofs = (KT_IDX) * 32 + loff * 8;                                      \
        const uint32_t db = sb + (ST) * STG_B + lrow * PITCH + loff * 16;               \
        cpasync16(db,                  Ahg + (long long)(m0 + lrow) * lda + kofs);      \
        cpasync16(db + 64 * PITCH,     Ahg + (long long)(m0 + lrow + 64) * lda + kofs); \
        cpasync16(db + MAT_B,          Alg + (long long)(m0 + lrow) * lda + kofs);      \
        cpasync16(db + MAT_B + 64 * PITCH, Alg + (long long)(m0 + lrow + 64) * lda + kofs); \
        cpasync16(db + 2 * MAT_B,      Bhg + (long long)(n0 + lrow) * ldb + kofs);      \
        cpasync16(db + 2 * MAT_B + 64 * PITCH, Bhg + (long long)(n0 + lrow + 64) * ldb + kofs); \
        cpasync16(db + 3 * MAT_B,      Blg + (long long)(n0 + lrow) * ldb + kofs);      \
        cpasync16(db + 3 * MAT_B + 64 * PITCH, Blg + (long long)(n0 + lrow + 64) * ldb + kofs); \
        asm volatile("cp.async.commit_group;");                                         \
    }

    LOAD_STAGE(0, 0);

    for (int kt = 0; kt < KT; kt++) {
        if (kt + 1 < KT) {
            LOAD_STAGE(kt + 1, (kt + 1) & 1);
            asm volatile("cp.async.wait_group 1;");
        } else {
            asm volatile("cp.async.wait_group 0;");
        }
        __syncthreads();

        const uint32_t base = sb + (kt & 1) * STG_B;
#pragma unroll
        for (int k16 = 0; k16 < 2; k16++) {
            const uint32_t kof = k16 * 32 + csel;
            uint32_t bh[4][2], bl[4][2];
#pragma unroll
            for (int np = 0; np < 2; np++) {
                const uint32_t rb = base + 2 * MAT_B + (wn + np * 16 + rsel) * PITCH + kof;
                uint32_t t0, t1, t2, t3;
                ldsm4(t0, t1, t2, t3, rb);
                bh[2 * np][0] = t0; bh[2 * np][1] = t2;
                bh[2 * np + 1][0] = t1; bh[2 * np + 1][1] = t3;
                ldsm4(t0, t1, t2, t3, rb + MAT_B);
                bl[2 * np][0] = t0; bl[2 * np][1] = t2;
                bl[2 * np + 1][0] = t1; bl[2 * np + 1][1] = t3;
            }
#pragma unroll
            for (int mg = 0; mg < 2; mg++) {
                uint32_t ah[2][4], al[2][4];
#pragma unroll
                for (int mi = 0; mi < 2; mi++) {
                    const uint32_t ra = base + (wm + (mg * 2 + mi) * 16 + rsel) * PITCH + kof;
                    ldsm4(ah[mi][0], ah[mi][1], ah[mi][2], ah[mi][3], ra);
                    ldsm4(al[mi][0], al[mi][1], al[mi][2], al[mi][3], ra + MAT_B);
                }
#pragma unroll
                for (int mi = 0; mi < 2; mi++)
#pragma unroll
                    for (int nf = 0; nf < 4; nf++)
                        mma16b(acc[mg * 2 + mi][nf], ah[mi], bh[nf]);
#pragma unroll
                for (int mi = 0; mi < 2; mi++)
#pragma unroll
                    for (int nf = 0; nf < 4; nf++)
                        mma16b(acc[mg * 2 + mi][nf], ah[mi], bl[nf]);
#pragma unroll
                for (int mi = 0; mi < 2; mi++)
#pragma unroll
                    for (int nf = 0; nf < 4; nf++)
                        mma16b(acc[mg * 2 + mi][nf], al[mi], bh[nf]);
            }
        }
        __syncthreads();
    }

#pragma unroll
    for (int mf = 0; mf < 4; mf++) {
        const int r = m0 + wm + mf * 16 + gid;
#pragma unroll
        for (int nf = 0; nf < 4; nf++) {
            const int c = n0 + wn + nf * 8 + 2 * tig;
            float b0 = bias ? bias[c] : 0.f;
            float b1 = bias ? bias[c + 1] : 0.f;
            float2 v0 = {alpha * acc[mf][nf][0] + b0, alpha * acc[mf][nf][1] + b1};
            float2 v1 = {alpha * acc[mf][nf][2] + b0, alpha * acc[mf][nf][3] + b1};
            *(float2*)&C[(long long)r * ldc + c] = v0;
            *(float2*)&C[(long long)(r + 8) * ldc + c] = v1;
        }
    }
}

// ===================== split / convert kernels =====================
__global__ void k_split(const float4* __restrict__ in, __nv_bfloat162* __restrict__ hi,
                        __nv_bfloat162* __restrict__ lo, int n4) {
    int i = blockIdx.x * 256 + threadIdx.x;
    if (i >= n4) return;
    float4 v = in[i];
    __nv_bfloat16 h0 = __float2bfloat16(v.x), h1 = __float2bfloat16(v.y);
    __nv_bfloat16 h2 = __float2bfloat16(v.z), h3 = __float2bfloat16(v.w);
    hi[2 * i]     = __nv_bfloat162(h0, h1);
    hi[2 * i + 1] = __nv_bfloat162(h2, h3);
    lo[2 * i]     = __nv_bfloat162(__float2bfloat16(v.x - __bfloat162float(h0)),
                                   __float2bfloat16(v.y - __bfloat162float(h1)));
    lo[2 * i + 1] = __nv_bfloat162(__float2bfloat16(v.z - __bfloat162float(h2)),
                                   __float2bfloat16(v.w - __bfloat162float(h3)));
}

__global__ void k_half(const float4* __restrict__ in, __half2* __restrict__ out, int n4) {
    int i = blockIdx.x * 256 + threadIdx.x;
    if (i >= n4) return;
    float4 v = in[i];
    out[2 * i]     = __half2(__float2half_rn(v.x), __float2half_rn(v.y));
    out[2 * i + 1] = __half2(__float2half_rn(v.z), __float2half_rn(v.w));
}

__global__ void __launch_bounds__(256) k_wout(const float4* __restrict__ wout,
                                              __half2* __restrict__ wo16) {
    int i = blockIdx.x * 256 + threadIdx.x;
    if (i >= 8192000) return;
    float4 v = wout[i];
    wo16[2 * i]     = __half2(__float2half_rn(v.x), __float2half_rn(v.y));
    wo16[2 * i + 1] = __half2(__float2half_rn(v.z), __float2half_rn(v.w));
}

// ===================== consolidated init =====================
__global__ void k_init(const int* __restrict__ y, const float* __restrict__ tab,
                       const float4* __restrict__ Wih,
                       const float* __restrict__ bih, const float* __restrict__ bhh) {
    const int bk = blockIdx.x, tid = threadIdx.x;
    if (bk < 512) {
        int i = bk * 256 + tid;
        int bs = i >> 6, e = i & 63;
        float4 v = ((const float4*)(tab + (long long)y[bs] * 256))[e];
        __nv_bfloat16 h0 = __float2bfloat16(v.x), h1 = __float2bfloat16(v.y);
        __nv_bfloat16 h2 = __float2bfloat16(v.z), h3 = __float2bfloat16(v.w);
        ((__nv_bfloat162*)s_emb_h)[2 * i]     = __nv_bfloat162(h0, h1);
        ((__nv_bfloat162*)s_emb_h)[2 * i + 1] = __nv_bfloat162(h2, h3);
        ((__nv_bfloat162*)s_emb_l)[2 * i]     = __nv_bfloat162(__float2bfloat16(v.x - __bfloat162float(h0)),
                                                               __float2bfloat16(v.y - __bfloat162float(h1)));
        ((__nv_bfloat162*)s_emb_l)[2 * i + 1] = __nv_bfloat162(__float2bfloat16(v.z - __bfloat162float(h2)),
                                                               __float2bfloat16(v.w - __bfloat162float(h3)));
    } else if (bk < 1024) {
        int i = (bk - 512) * 256 + tid;
        float4 v = Wih[i];
        __nv_bfloat16 h0 = __float2bfloat16(v.x), h1 = __float2bfloat16(v.y);
        __nv_bfloat16 h2 = __float2bfloat16(v.z), h3 = __float2bfloat16(v.w);
        ((__nv_bfloat162*)s_wih_h)[2 * i]     = __nv_bfloat162(h0, h1);
        ((__nv_bfloat162*)s_wih_h)[2 * i + 1] = __nv_bfloat162(h2, h3);
        ((__nv_bfloat162*)s_wih_l)[2 * i]     = __nv_bfloat162(__float2bfloat16(v.x - __bfloat162float(h0)),
                                                               __float2bfloat16(v.y - __bfloat162float(h1)));
        ((__nv_bfloat162*)s_wih_l)[2 * i + 1] = __nv_bfloat162(__float2bfloat16(v.z - __bfloat162float(h2)),
                                                               __float2bfloat16(v.w - __bfloat162float(h3)));
    } else {
        int i = (bk - 1024) * 256 + tid;
        if (i < 2048) g_bcomb[i] = bih[i] + bhh[i];
        if (i < 8192) g_hbuf[i] = 0.f;
        if (i < 2) g_bar2[i] = 0;
    }
}

__global__ void k_transpose(const float* __restrict__ in, float* __restrict__ out, int R, int C) {
    __shared__ float t[32][33];
    in += (long long)blockIdx.z * R * C;
    out += (long long)blockIdx.z * R * C;
    int c0 = blockIdx.x * 32, r0 = blockIdx.y * 32;
    int x = threadIdx.x, y = threadIdx.y;
#pragma unroll
    for (int i = 0; i < 32; i += 8)
        if (r0 + y + i < R && c0 + x < C) t[y + i][x] = in[(r0 + y + i) * C + c0 + x];
    __syncthreads();
#pragma unroll
    for (int i = 0; i < 32; i += 8)
        if (c0 + y + i < C && r0 + x < R) out[(c0 + y + i) * R + r0 + x] = t[x][y + i];
}

__global__ void k_softmax(const uint32_t* __restrict__ mask) {
    int w = (blockIdx.x * blockDim.x + threadIdx.x) >> 5;
    int lane = threadIdx.x & 31;
    if (w >= 2048) return;
    int b = w >> 7;
    const float* row = g_scores + w * 128;
    const uint32_t* m = mask + b * 128;
    float v[4];
    float mx = -1e30f;
#pragma unroll
    for (int i = 0; i < 4; i++) {
        int l = lane + 32 * i;
        v[i] = (m[l] != 0u) ? row[l] : -1e9f;
        mx = fmaxf(mx, v[i]);
    }
#pragma unroll
    for (int o = 16; o > 0; o >>= 1) mx = fmaxf(mx, __shfl_xor_sync(0xffffffffu, mx, o));
    float s = 0.f;
#pragma unroll
    for (int i = 0; i < 4; i++) { v[i] = expf(v[i] - mx); s += v[i]; }
#pragma unroll
    for (int o = 16; o > 0; o >>= 1) s += __shfl_xor_sync(0xffffffffu, s, o);
    float inv = 1.f / s;
#pragma unroll
    for (int i = 0; i < 4; i++) {
        float p = v[i] * inv;
        __nv_bfloat16 h = __float2bfloat16(p);
        int idx = w * 128 + lane + 32 * i;
        s_sc_h[idx] = h;
        s_sc_l[idx] = __float2bfloat16(p - __bfloat162float(h));
    }
}

// ===================== LSTM: 2 de-phased groups x 128 blocks, fast transcendentals ====
#define LSTM_SMEM ((8320 + 4160 + 2048 + 128) * 4)   // 58624 B

__global__ void __launch_bounds__(128, 2) lstm_kernel(const float* __restrict__ xw) {
    const int tid = threadIdx.x, bk = blockIdx.x;
    const int gr = bk >> 7, bi = bk & 127;
    const int u0 = bi * 4;

    extern __shared__ float smf[];
    float* w_sm = smf;            // k*16 + (k>>5)*8 + jl
    float* h_sm = smf + 8320;     // k*8  + (k>>5)*4 + b
    float* red = smf + 12480;     // [16ks][16jl][8b]
    float* sgate = smf + 14528;   // [16jl][8b]

    float* ghb = g_hbuf + gr * 4096;
    unsigned* barp = &g_bar2[gr];

    for (int i = tid; i < 2048; i += 128) {
        int k = i >> 2, g = i & 3;
        ((float4*)w_sm)[k * 4 + (k >> 5) * 2 + g] =
            *(const float4*)(g_whhT + k * 2048 + g * 512 + u0);
    }

    const int ks = tid >> 3;
    const int jl0 = (tid & 7) * 2;
    const int rjl = tid >> 3, rbb = tid & 7;
    const int gx = rjl >> 2, uux = rjl & 3;
    const int puu = tid >> 3, pb = tid & 7;
    float creg = 0.f;

    const float* xwp = xw + (long long)((gr * 8 + rbb) * 128) * 2048 + gx * 512 + u0 + uux;
    float xw_cur = xwp[0];
    __syncthreads();

    // de-phase: group 1 starts ~half a step later so the two co-resident blocks
    // on each SM alternate compute <-> barrier-stall instead of coinciding.
    if (gr == 1) {
        long long s0 = clock64();
        while (clock64() - s0 < 3500) {}
    }

    for (int t = 0; t < 128; t++) {
#pragma unroll
        for (int i = tid; i < 1024; i += 128) {
            int k = i >> 1, half = i & 1;
            ((float4*)h_sm)[k * 2 + (k >> 5) + half] = ((const float4*)ghb)[i];
        }
        __syncthreads();

        float a[2][8];
#pragma unroll
        for (int jj = 0; jj < 2; jj++)
#pragma unroll
            for (int bb = 0; bb < 8; bb++) a[jj][bb] = 0.f;

        const float* wp = w_sm + ks * 520 + jl0;
        const float* hp = h_sm + ks * 260;
#pragma unroll 8
        for (int k = 0; k < 32; k++) {
            float2 wv = *(const float2*)(wp + k * 16);
            float4 h0 = *(const float4*)(hp + k * 8);
            float4 h1 = *(const float4*)(hp + k * 8 + 4);
            float hb[8] = {h0.x, h0.y, h0.z, h0.w, h1.x, h1.y, h1.z, h1.w};
#pragma unroll
            for (int bb = 0; bb < 8; bb++) {
                a[0][bb] = fmaf(wv.x, hb[bb], a[0][bb]);
                a[1][bb] = fmaf(wv.y, hb[bb], a[1][bb]);
            }
        }
#pragma unroll
        for (int jj = 0; jj < 2; jj++)
#pragma unroll
            for (int bb = 0; bb < 8; bb++)
                red[ks * 128 + (jl0 + jj) * 8 + bb] = a[jj][bb];
        __syncthreads();

        float s = 0.f;
#pragma unroll
        for (int q = 0; q < 16; q++) s += red[q * 128 + rjl * 8 + rbb];
        s += xw_cur;
        // parallel gate transform: rjl = g*4+uu; gate type g = rjl>>2 (2 = cell gate)
        sgate[rjl * 8 + rbb] = ((rjl >> 2) == 2) ? ftanh(s) : fsigm(s);
        __syncthreads();

        if (tid < 32) {
            float ti = sgate[(0 * 4 + puu) * 8 + pb];
            float tf = sgate[(1 * 4 + puu) * 8 + pb];
            float tg = sgate[(2 * 4 + puu) * 8 + pb];
            float to = sgate[(3 * 4 + puu) * 8 + pb];
            creg = tf * creg + ti * tg;
            float h = to * ftanh(creg);
            ghb[(u0 + puu) * 8 + pb] = h;
            g_cat[((gr * 8 + pb) * 128 + t) * 1024 + u0 + puu] = h;
        }
        if (t + 1 < 128) xw_cur = xwp[(t + 1) * 2048];

        __syncthreads();
        if (tid == 0) {
            __threadfence();
            atomicAdd(barp, 1);
            unsigned target = 128u * (t + 1);
            while (*(volatile unsigned*)barp < target) __nanosleep(32);
            __threadfence();
        }
        __syncthreads();
    }
}

// ===================== host launcher =====================
extern "C" void kernel_launch(void* const* d_in, const int* in_sizes, int n_in,
                              void* d_out, int out_size) {
    const int* y = (const int*)d_in[0];
    const float* tab = (const float*)d_in[1];
    const float* Wih = (const float*)d_in[2];
    const float* Whh = (const float*)d_in[3];
    const float* bih = (const float*)d_in[4];
    const float* bhh = (const float*)d_in[5];
    const float* enc = (const float*)d_in[6];
    const uint32_t* mask = (const uint32_t*)d_in[7];
    const float* Wout = (const float*)d_in[8];
    const float* bout = (const float*)d_in[9];
    float* out = (float*)d_out;

    float *p_xw, *p_cat, *p_scores, *p_encT, *p_whhT, *p_bcomb;
    cudaGetSymbolAddress((void**)&p_xw, g_xw);
    cudaGetSymbolAddress((void**)&p_cat, g_cat);
    cudaGetSymbolAddress((void**)&p_scores, g_scores);
    cudaGetSymbolAddress((void**)&p_encT, g_encT);
    cudaGetSymbolAddress((void**)&p_whhT, g_whhT);
    cudaGetSymbolAddress((void**)&p_bcomb, g_bcomb);

    __nv_bfloat16 *e_h, *e_l, *wi_h, *wi_l, *c_h, *c_l;
    __nv_bfloat16 *en_h, *en_l, *et_h, *et_l, *sc_h, *sc_l;
    cudaGetSymbolAddress((void**)&e_h, s_emb_h);   cudaGetSymbolAddress((void**)&e_l, s_emb_l);
    cudaGetSymbolAddress((void**)&wi_h, s_wih_h);  cudaGetSymbolAddress((void**)&wi_l, s_wih_l);
    cudaGetSymbolAddress((void**)&c_h, s_cat_h);   cudaGetSymbolAddress((void**)&c_l, s_cat_l);
    cudaGetSymbolAddress((void**)&en_h, s_enc_h);  cudaGetSymbolAddress((void**)&en_l, s_enc_l);
    cudaGetSymbolAddress((void**)&et_h, s_encT_h); cudaGetSymbolAddress((void**)&et_l, s_encT_l);
    cudaGetSymbolAddress((void**)&sc_h, s_sc_h);   cudaGetSymbolAddress((void**)&sc_l, s_sc_l);

    __half *c16, *wo16;
    cudaGetSymbolAddress((void**)&c16, s_cat16);
    cudaGetSymbolAddress((void**)&wo16, s_wout16);

    cudaFuncSetAttribute(gemmb, cudaFuncAttributeMaxDynamicSharedMemorySize, 2 * STG_B);
    cudaFuncSetAttribute(gemmh, cudaFuncAttributeMaxDynamicSharedMemorySize, HSMEM);
    cudaFuncSetAttribute(lstm_kernel, cudaFuncAttributeMaxDynamicSharedMemorySize, LSTM_SMEM);

    // #1: consolidated init
    k_init<<<1056, 256>>>(y, tab, (const float4*)Wih, bih, bhh);

    // #2: xw = emb @ W_ih^T + (b_ih + b_hh)   [bf16 3-term]
    gemmb<<<dim3(16, 16, 1), 256, 2 * STG_B>>>(e_h, e_l, wi_h, wi_l, p_xw, p_bcomb,
                                               256, 256, 256, 2048, 0, 0, 0, 1.f);

    // #3: W_hh transpose
    k_transpose<<<dim3(16, 64, 1), dim3(32, 8)>>>(Whh, p_whhT, 2048, 512);

    // #4: LSTM, 2 de-phased groups   <-- ncu-profiled launch
    lstm_kernel<<<256, 128, LSTM_SMEM>>>(p_xw);

    // #5: W_out fp16 conversion
    k_wout<<<32000, 256>>>((const float4*)Wout, (__half2*)wo16);

    // enc prep
    k_transpose<<<dim3(16, 4, 16), dim3(32, 8)>>>(enc, p_encT, 128, 512);
    k_split<<<1024, 256>>>((const float4*)enc, (__nv_bfloat162*)en_h, (__nv_bfloat162*)en_l, 262144);
    k_split<<<1024, 256>>>((const float4*)p_encT, (__nv_bfloat162*)et_h, (__nv_bfloat162*)et_l, 262144);

    k_split<<<2048, 256>>>((const float4*)p_cat, (__nv_bfloat162*)c_h, (__nv_bfloat162*)c_l, 524288);

    // scores = dec @ enc^T / sqrt(H)        [bf16 3-term]
    gemmb<<<dim3(1, 1, 16), 256, 2 * STG_B>>>(c_h, c_l, en_h, en_l, p_scores, nullptr,
                                              512, 1024, 512, 128,
                                              131072LL, 65536LL, 16384LL,
                                              0.044194173824159216f);
    k_softmax<<<256, 256>>>(mask);

    // context = probs @ enc                 [bf16 3-term]
    gemmb<<<dim3(1, 4, 16), 256, 2 * STG_B>>>(sc_h, sc_l, et_h, et_l, p_cat + 512, nullptr,
                                              128, 128, 128, 1024,
                                              16384LL, 65536LL, 131072LL, 1.f);

    // cat -> fp16
    k_half<<<2048, 256>>>((const float4*)p_cat, (__half2*)c16, 524288);

    // logits = cat @ W_out^T + b_out        [fp16 1-term]
    gemmh<<<dim3(16, 250), 256, HSMEM>>>(c16, wo16, out, bout, 1024, 1024, 1024, 32000);
}